// round 10
// baseline (speedup 1.0000x reference)
#include <cuda_runtime.h>
#include <cuda_bf16.h>
#include <cstdint>

#define NN   100000
#define NE   1600000
#define NGR  128
#define D_   128
#define DO_  64
#define BN_EPS 1e-5f
#define SCAN_ELEMS 2048
#define NBLK ((NN + SCAN_ELEMS - 1) / SCAN_ELEMS)   // 49

typedef unsigned long long ull;

// ---------------- scratch ----------------
__device__ __align__(16) float g_h1 [(size_t)NN * D_];
__device__ __align__(16) float g_h2 [(size_t)NN * D_];
__device__ __align__(16) float g_bnstats[2 * D_];   // zero at module init; finalize re-zeroes
__device__ __align__(16) float g_scale[D_];
__device__ __align__(16) float g_shift[D_];
__device__ __align__(16) float g_pool[NGR * DO_];
__device__ __align__(16) int   g_cnt[NGR];
// CSR scratch
__device__ __align__(16) int g_deg[NN];             // zero at init; scan3 re-zeroes
__device__ __align__(16) int g_off[NN + 1];
__device__ __align__(16) int g_cur[NN];
__device__ __align__(16) int g_csr[NE];
__device__ int g_bsum[64];
__device__ int g_bscan[64];
// pre-split, pre-swizzled W images: [k][n] row-major bf16, 16B-chunk XOR swizzle
__device__ __align__(16) unsigned char g_whi[6 * 32768];
__device__ __align__(16) unsigned char g_wlo[6 * 32768];

// ---------------- asm helpers ----------------
__device__ __forceinline__ uint32_t smem_u32(const void* p) {
    uint32_t a;
    asm("{ .reg .u64 t; cvta.to.shared.u64 t, %1; cvt.u32.u64 %0, t; }" : "=r"(a) : "l"(p));
    return a;
}
__device__ __forceinline__ void ldsm_x4(uint32_t& r0, uint32_t& r1, uint32_t& r2, uint32_t& r3,
                                        uint32_t addr) {
    asm volatile("ldmatrix.sync.aligned.m8n8.x4.shared.b16 {%0,%1,%2,%3}, [%4];"
                 : "=r"(r0), "=r"(r1), "=r"(r2), "=r"(r3) : "r"(addr));
}
__device__ __forceinline__ void ldsm_x4t(uint32_t& r0, uint32_t& r1, uint32_t& r2, uint32_t& r3,
                                         uint32_t addr) {
    asm volatile("ldmatrix.sync.aligned.m8n8.x4.trans.shared.b16 {%0,%1,%2,%3}, [%4];"
                 : "=r"(r0), "=r"(r1), "=r"(r2), "=r"(r3) : "r"(addr));
}
__device__ __forceinline__ void mma16816(float* c, uint32_t a0, uint32_t a1, uint32_t a2,
                                         uint32_t a3, uint32_t b0, uint32_t b1) {
    asm volatile("mma.sync.aligned.m16n8k16.row.col.f32.bf16.bf16.f32 "
                 "{%0,%1,%2,%3}, {%4,%5,%6,%7}, {%8,%9}, {%0,%1,%2,%3};"
                 : "+f"(c[0]), "+f"(c[1]), "+f"(c[2]), "+f"(c[3])
                 : "r"(a0), "r"(a1), "r"(a2), "r"(a3), "r"(b0), "r"(b1));
}

// ---------------- CSR build ----------------
__global__ void hist_kernel(const int* __restrict__ dst) {
    int i = blockIdx.x * blockDim.x + threadIdx.x;
    if (i < NE) atomicAdd(&g_deg[__ldg(dst + i)], 1);
}
__global__ void scan_pass1() {
    __shared__ int ssum[8];
    int b = blockIdx.x, tid = threadIdx.x;
    int base = b * SCAN_ELEMS + tid * 8;
    int s = 0;
    #pragma unroll
    for (int j = 0; j < 8; j++) { int idx = base + j; s += (idx < NN) ? g_deg[idx] : 0; }
    #pragma unroll
    for (int o = 16; o; o >>= 1) s += __shfl_down_sync(0xffffffffu, s, o);
    if ((tid & 31) == 0) ssum[tid >> 5] = s;
    __syncthreads();
    if (tid == 0) {
        int t = 0;
        #pragma unroll
        for (int i = 0; i < 8; i++) t += ssum[i];
        g_bsum[b] = t;
    }
}
__global__ void scan_pass2() {
    int tid = threadIdx.x;
    int v = (tid < NBLK) ? g_bsum[tid] : 0;
    int incl = v, lane = tid & 31;
    #pragma unroll
    for (int o = 1; o < 32; o <<= 1) {
        int y = __shfl_up_sync(0xffffffffu, incl, o);
        if (lane >= o) incl += y;
    }
    __shared__ int w0;
    if (tid == 31) w0 = incl;
    __syncthreads();
    if (tid >= 32) incl += w0;
    if (tid < 64) g_bscan[tid] = incl - v;
    if (tid == 0) g_off[NN] = NE;
}
__global__ void scan_pass3() {
    int b = blockIdx.x, tid = threadIdx.x;
    int base = b * SCAN_ELEMS + tid * 8;
    int vals[8], t = 0;
    #pragma unroll
    for (int j = 0; j < 8; j++) { vals[j] = (base + j < NN) ? g_deg[base + j] : 0; t += vals[j]; }
    int lane = tid & 31, wid = tid >> 5, incl = t;
    #pragma unroll
    for (int o = 1; o < 32; o <<= 1) {
        int y = __shfl_up_sync(0xffffffffu, incl, o);
        if (lane >= o) incl += y;
    }
    __shared__ int wsum[8], woff[8];
    if (lane == 31) wsum[wid] = incl;
    __syncthreads();
    if (tid == 0) { int a = 0; for (int i = 0; i < 8; i++) { woff[i] = a; a += wsum[i]; } }
    __syncthreads();
    int run = g_bscan[b] + woff[wid] + (incl - t);
    #pragma unroll
    for (int j = 0; j < 8; j++) {
        int idx = base + j;
        if (idx < NN) {
            g_off[idx] = run; g_cur[idx] = run; run += vals[j];
            g_deg[idx] = 0;   // reset for next replay
        }
    }
}
__global__ void fill_kernel(const int* __restrict__ src, const int* __restrict__ dst) {
    int i = blockIdx.x * blockDim.x + threadIdx.x;
    if (i < NE) {
        int d = __ldg(dst + i);
        int p = atomicAdd(&g_cur[d], 1);
        g_csr[p] = __ldg(src + i);
    }
}

// ---------------- W split + swizzle preconvert (+ pool/cnt zeroing) ----------------
__global__ void wconv_kernel(const float* w0, const float* w1, const float* w2,
                             const float* w3, const float* w4, const float* w5)
{
    int i = blockIdx.x * blockDim.x + threadIdx.x;
    if (i < NGR * DO_) g_pool[i] = 0.f;
    if (i < NGR) g_cnt[i] = 0;
    if (i >= 5 * 16384 + 8192) return;
    int seg = i >> 14;
    int t = i & 16383;
    int nout = (seg == 5) ? 64 : 128;
    const float* W = (seg == 0) ? w0 : (seg == 1) ? w1 : (seg == 2) ? w2
                   : (seg == 3) ? w3 : (seg == 4) ? w4 : w5;
    int k = t / nout, n = t % nout;
    float w = __ldg(W + k * nout + n);
    __nv_bfloat16 hi = __float2bfloat16(w);
    __nv_bfloat16 lo = __float2bfloat16(w - __bfloat162float(hi));
    int pos = k * nout + ((((n >> 3) ^ (k & 7)) << 3) | (n & 7));
    ((__nv_bfloat16*)(g_whi + seg * 32768))[pos] = hi;
    ((__nv_bfloat16*)(g_wlo + seg * 32768))[pos] = lo;
}

// ---------------- helpers ----------------
__device__ __forceinline__ float4 bn_ap(float4 v, float4 sc, float4 sh, bool bn) {
    if (bn) {
        v.x = fmaxf(fmaf(v.x, sc.x, sh.x), 0.f);
        v.y = fmaxf(fmaf(v.y, sc.y, sh.y), 0.f);
        v.z = fmaxf(fmaf(v.z, sc.z, sh.z), 0.f);
        v.w = fmaxf(fmaf(v.w, sc.w, sh.w), 0.f);
    }
    return v;
}
__device__ __forceinline__ void f4acc(float4& a, float4 b) {
    a.x += b.x; a.y += b.y; a.z += b.z; a.w += b.w;
}

// ---------------- mma_loop (shared by both stages) ----------------
template<int NT>
__device__ __forceinline__ void mma_loop(uint32_t sb, uint32_t aHi, uint32_t aLo,
                                         uint32_t bHi, uint32_t bLo,
                                         int wid, int lane, float acc[][4])
{
    const int la = lane & 15;
    const int lb = lane >> 4;
    const int l7 = lane & 7;
    const int BR = NT * 16;
    const uint32_t aRow = (uint32_t)((wid * 16 + la) * 256);
    const uint32_t bRow = (uint32_t)(la * BR);
    #pragma unroll 2
    for (int k0 = 0; k0 < 128; k0 += 16) {
        uint32_t kc = (uint32_t)((k0 >> 3) + lb);
        uint32_t aoff = aRow + ((kc ^ (uint32_t)l7) << 4);
        uint32_t ah0, ah1, ah2, ah3, al0, al1, al2, al3;
        ldsm_x4(ah0, ah1, ah2, ah3, sb + aHi + aoff);
        ldsm_x4(al0, al1, al2, al3, sb + aLo + aoff);
        uint32_t bbase = (uint32_t)(k0 * BR) + bRow;
        #pragma unroll
        for (int nt = 0; nt < NT; nt += 2) {
            uint32_t boff = bbase + ((((uint32_t)(nt + lb)) ^ (uint32_t)l7) << 4);
            uint32_t bh0, bh1, bh2, bh3, bl0, bl1, bl2, bl3;
            ldsm_x4t(bh0, bh1, bh2, bh3, sb + bHi + boff);
            ldsm_x4t(bl0, bl1, bl2, bl3, sb + bLo + boff);
            mma16816(acc[nt],     ah0, ah1, ah2, ah3, bh0, bh1);
            mma16816(acc[nt + 1], ah0, ah1, ah2, ah3, bh2, bh3);
            mma16816(acc[nt],     ah0, ah1, ah2, ah3, bl0, bl1);
            mma16816(acc[nt + 1], ah0, ah1, ah2, ah3, bl2, bl3);
            mma16816(acc[nt],     al0, al1, al2, al3, bh0, bh1);
            mma16816(acc[nt + 1], al0, al1, al2, al3, bh2, bh3);
        }
    }
}

// ---------------- fused GIN layer: gather + 2-GEMM MLP in one kernel ----------------
// out[N,NOUT] = ReLU( (agg of f(h)) @ W1 + b1 ) @ W2 + b2
// where f = BN+ReLU of previous layer (BN template) or identity.
// Gather phase writes split-bf16 A-tiles directly into swizzled smem.
template<int NOUT, bool BN>
__global__ __launch_bounds__(256, 1)
void gin_layer(const float* __restrict__ h,
               const unsigned char* __restrict__ w1h, const unsigned char* __restrict__ w1l,
               const float* __restrict__ b1,
               const unsigned char* __restrict__ w2h, const unsigned char* __restrict__ w2l,
               const float* __restrict__ b2, float* __restrict__ out)
{
    constexpr int NT2  = NOUT / 8;
    constexpr int AHI  = 0;
    constexpr int ALO  = 32768;
    constexpr int B1HI = 65536;
    constexpr int B1LO = 98304;
    constexpr int B2HI = 131072;
    constexpr int B2LO = 131072 + NOUT * 256;

    extern __shared__ __align__(16) char smem[];
    const uint32_t sb = smem_u32(smem);
    const int tid  = threadIdx.x;
    const int wid  = tid >> 5;
    const int lane = tid & 31;
    const int row0 = blockIdx.x * 128;

    // B tiles: straight copies of pre-swizzled images
    {
        const float4* s1 = (const float4*)w1h;
        const float4* s2 = (const float4*)w1l;
        float4* d1 = (float4*)(smem + B1HI);
        float4* d2 = (float4*)(smem + B1LO);
        #pragma unroll
        for (int i = tid; i < 2048; i += 256) { d1[i] = s1[i]; d2[i] = s2[i]; }
        const float4* s3 = (const float4*)w2h;
        const float4* s4 = (const float4*)w2l;
        float4* d3 = (float4*)(smem + B2HI);
        float4* d4 = (float4*)(smem + B2LO);
        #pragma unroll
        for (int i = tid; i < NOUT * 16; i += 256) { d3[i] = s3[i]; d4[i] = s4[i]; }
    }

    // ---- gather phase: 8 warps x 16 iterations cover 128 rows ----
    {
        const float4* __restrict__ h4 = (const float4*)h;
        float4 sc = make_float4(0,0,0,0), sh = make_float4(0,0,0,0);
        if (BN) {
            sc = *(const float4*)(g_scale + lane * 4);
            sh = *(const float4*)(g_shift + lane * 4);
        }
        // smem target: lane covers dims [4*lane, 4*lane+4) = bf16 bytes [8*lane, 8*lane+8)
        // 16B chunk c = lane>>1, half = lane&1
        const uint32_t chunk = (uint32_t)(lane >> 1);
        const uint32_t half8 = (uint32_t)((lane & 1) * 8);

        #pragma unroll 1
        for (int it = 0; it < 16; it++) {
            int r = it * 8 + wid;          // local row
            int n = row0 + r;
            float4 a0 = make_float4(0,0,0,0);
            if (n < NN) {
                a0 = bn_ap(__ldg(&h4[(size_t)n * 32 + lane]), sc, sh, BN);  // self
                float4 a1 = make_float4(0,0,0,0), a2 = make_float4(0,0,0,0), a3 = make_float4(0,0,0,0);
                int j = g_off[n], e1 = g_off[n + 1];
                for (; j + 4 <= e1; j += 4) {
                    int i0 = __ldg(&g_csr[j]);
                    int i1 = __ldg(&g_csr[j + 1]);
                    int i2 = __ldg(&g_csr[j + 2]);
                    int i3 = __ldg(&g_csr[j + 3]);
                    float4 w0 = __ldg(&h4[(size_t)i0 * 32 + lane]);
                    float4 w1 = __ldg(&h4[(size_t)i1 * 32 + lane]);
                    float4 w2 = __ldg(&h4[(size_t)i2 * 32 + lane]);
                    float4 w3 = __ldg(&h4[(size_t)i3 * 32 + lane]);
                    f4acc(a0, bn_ap(w0, sc, sh, BN));
                    f4acc(a1, bn_ap(w1, sc, sh, BN));
                    f4acc(a2, bn_ap(w2, sc, sh, BN));
                    f4acc(a3, bn_ap(w3, sc, sh, BN));
                }
                for (; j < e1; j++) {
                    int s = __ldg(&g_csr[j]);
                    f4acc(a0, bn_ap(__ldg(&h4[(size_t)s * 32 + lane]), sc, sh, BN));
                }
                f4acc(a0, a1); f4acc(a2, a3); f4acc(a0, a2);
            }
            // split to bf16 hi/lo and store swizzled (8 bytes each)
            __nv_bfloat162 h2a, h2b, l2a, l2b;
            h2a.x = __float2bfloat16(a0.x);
            h2a.y = __float2bfloat16(a0.y);
            h2b.x = __float2bfloat16(a0.z);
            h2b.y = __float2bfloat16(a0.w);
            l2a.x = __float2bfloat16(a0.x - __bfloat162float(h2a.x));
            l2a.y = __float2bfloat16(a0.y - __bfloat162float(h2a.y));
            l2b.x = __float2bfloat16(a0.z - __bfloat162float(h2b.x));
            l2b.y = __float2bfloat16(a0.w - __bfloat162float(h2b.y));
            uint2 hq, lq;
            hq.x = *(uint32_t*)&h2a; hq.y = *(uint32_t*)&h2b;
            lq.x = *(uint32_t*)&l2a; lq.y = *(uint32_t*)&l2b;
            uint32_t off = (uint32_t)(r * 256) + ((chunk ^ (uint32_t)(r & 7)) << 4) + half8;
            *(uint2*)(smem + AHI + off) = hq;
            *(uint2*)(smem + ALO + off) = lq;
        }
    }
    __syncthreads();

    // ---- stage 1: hid = ReLU(A @ W1 + b1) ----
    float acc[16][4];
    #pragma unroll
    for (int t = 0; t < 16; t++)
        #pragma unroll
        for (int e = 0; e < 4; e++) acc[t][e] = 0.f;
    mma_loop<16>(sb, AHI, ALO, B1HI, B1LO, wid, lane, acc);
    __syncthreads();   // all warps done reading A tile

    // epilogue 1: bias+ReLU, split to bf16, write back into A buffers (swizzled)
    {
        int rr1 = wid * 16 + (lane >> 2);
        int rr2 = rr1 + 8;
        uint32_t cb1 = (uint32_t)(rr1 * 256);
        uint32_t cb2 = (uint32_t)(rr2 * 256);
        int sw1 = (rr1 & 7), sw2 = (rr2 & 7);
        int cpos = (lane & 3) * 4;
        #pragma unroll
        for (int nt = 0; nt < 16; nt++) {
            int col = nt * 8 + (lane & 3) * 2;
            float2 bb = __ldg((const float2*)(b1 + col));
            float v0 = fmaxf(acc[nt][0] + bb.x, 0.f);
            float v1 = fmaxf(acc[nt][1] + bb.y, 0.f);
            float v2 = fmaxf(acc[nt][2] + bb.x, 0.f);
            float v3 = fmaxf(acc[nt][3] + bb.y, 0.f);
            __nv_bfloat162 h2, l2;
            h2.x = __float2bfloat16(v0);
            h2.y = __float2bfloat16(v1);
            l2.x = __float2bfloat16(v0 - __bfloat162float(h2.x));
            l2.y = __float2bfloat16(v1 - __bfloat162float(h2.y));
            uint32_t o1 = cb1 + ((uint32_t)(nt ^ sw1) << 4) + cpos;
            *(uint32_t*)(smem + AHI + o1) = *(uint32_t*)&h2;
            *(uint32_t*)(smem + ALO + o1) = *(uint32_t*)&l2;
            h2.x = __float2bfloat16(v2);
            h2.y = __float2bfloat16(v3);
            l2.x = __float2bfloat16(v2 - __bfloat162float(h2.x));
            l2.y = __float2bfloat16(v3 - __bfloat162float(h2.y));
            uint32_t o2 = cb2 + ((uint32_t)(nt ^ sw2) << 4) + cpos;
            *(uint32_t*)(smem + AHI + o2) = *(uint32_t*)&h2;
            *(uint32_t*)(smem + ALO + o2) = *(uint32_t*)&l2;
        }
    }
    __syncthreads();

    // ---- stage 2: out = hid @ W2 + b2 ----
    float acc2[NT2][4];
    #pragma unroll
    for (int t = 0; t < NT2; t++)
        #pragma unroll
        for (int e = 0; e < 4; e++) acc2[t][e] = 0.f;
    mma_loop<NT2>(sb, AHI, ALO, B2HI, B2LO, wid, lane, acc2);

    int r1 = row0 + wid * 16 + (lane >> 2);
    int r2 = r1 + 8;
    #pragma unroll
    for (int nt = 0; nt < NT2; nt++) {
        int col = nt * 8 + (lane & 3) * 2;
        float2 bb = __ldg((const float2*)(b2 + col));
        float v0 = acc2[nt][0] + bb.x;
        float v1 = acc2[nt][1] + bb.y;
        float v2 = acc2[nt][2] + bb.x;
        float v3 = acc2[nt][3] + bb.y;
        if (r1 < NN) *(float2*)(out + (size_t)r1 * NOUT + col) = make_float2(v0, v1);
        if (r2 < NN) *(float2*)(out + (size_t)r2 * NOUT + col) = make_float2(v2, v3);
    }
}

// ---------------- BN column stats (separate, coalesced) ----------------
template<int NOUT>
__global__ void stats_kernel(const float* __restrict__ h)
{
    constexpr int QC = NOUT / 4;
    constexpr int STEP = 256 / QC;
    __shared__ float ss[NOUT], sq[NOUT];
    int tid = threadIdx.x;
    if (tid < NOUT) { ss[tid] = 0.f; sq[tid] = 0.f; }
    __syncthreads();
    int qc = tid % QC, rg = tid / QC;
    int rend = min(blockIdx.x * 512 + 512, NN);
    float4 s4 = make_float4(0,0,0,0), q4 = make_float4(0,0,0,0);
    for (int r = blockIdx.x * 512 + rg; r < rend; r += STEP) {
        float4 v = __ldg((const float4*)(h + (size_t)r * NOUT) + qc);
        s4.x += v.x; s4.y += v.y; s4.z += v.z; s4.w += v.w;
        q4.x += v.x*v.x; q4.y += v.y*v.y; q4.z += v.z*v.z; q4.w += v.w*v.w;
    }
    int c = qc * 4;
    atomicAdd(&ss[c+0], s4.x); atomicAdd(&ss[c+1], s4.y);
    atomicAdd(&ss[c+2], s4.z); atomicAdd(&ss[c+3], s4.w);
    atomicAdd(&sq[c+0], q4.x); atomicAdd(&sq[c+1], q4.y);
    atomicAdd(&sq[c+2], q4.z); atomicAdd(&sq[c+3], q4.w);
    __syncthreads();
    if (tid < NOUT) {
        atomicAdd(&g_bnstats[tid], ss[tid]);
        atomicAdd(&g_bnstats[NOUT + tid], sq[tid]);
    }
}

// ---------------- BN finalize (resets stats after read) ----------------
__global__ void bn_finalize_kernel(const float* __restrict__ gamma,
                                   const float* __restrict__ beta, int nout)
{
    int c = threadIdx.x;
    if (c < nout) {
        const float invN = 1.0f / (float)NN;
        float sv = g_bnstats[c];
        float qv = g_bnstats[nout + c];
        float mu  = sv * invN;
        float var = qv * invN - mu * mu;
        float s   = gamma[c] * rsqrtf(var + BN_EPS);
        g_scale[c] = s;
        g_shift[c] = beta[c] - mu * s;
        g_bnstats[c] = 0.f;
        g_bnstats[nout + c] = 0.f;
    }
}

// ---------------- pooling (BN+ReLU fused) ----------------
__global__ void pool_sum_kernel(const float* __restrict__ pre, const int* __restrict__ batch)
{
    int t = blockIdx.x * blockDim.x + threadIdx.x;
    if (t >= NN * 16) return;
    int n = t >> 4, q = t & 15;
    int c = q << 2;
    int b = __ldg(batch + n);
    float4 v  = *(const float4*)(pre + (size_t)n * DO_ + c);
    float4 sc = *(const float4*)(g_scale + c);
    float4 sh = *(const float4*)(g_shift + c);
    v.x = fmaxf(fmaf(v.x, sc.x, sh.x), 0.f);
    v.y = fmaxf(fmaf(v.y, sc.y, sh.y), 0.f);
    v.z = fmaxf(fmaf(v.z, sc.z, sh.z), 0.f);
    v.w = fmaxf(fmaf(v.w, sc.w, sh.w), 0.f);
    float* p = g_pool + b * DO_ + c;
    asm volatile("red.global.add.v4.f32 [%0], {%1, %2, %3, %4};"
                 :: "l"(p), "f"(v.x), "f"(v.y), "f"(v.z), "f"(v.w) : "memory");
}

__global__ void pool_cnt_kernel(const int* __restrict__ batch)
{
    __shared__ int sc[NGR];
    for (int i = threadIdx.x; i < NGR; i += blockDim.x) sc[i] = 0;
    __syncthreads();
    for (int i = blockIdx.x * blockDim.x + threadIdx.x; i < NN; i += gridDim.x * blockDim.x)
        atomicAdd(&sc[__ldg(batch + i)], 1);
    __syncthreads();
    for (int i = threadIdx.x; i < NGR; i += blockDim.x)
        if (sc[i]) atomicAdd(&g_cnt[i], sc[i]);
}

__global__ void pool_fin_kernel(float* __restrict__ out)
{
    int i = blockIdx.x * blockDim.x + threadIdx.x;
    if (i < NGR * DO_) {
        int g = i >> 6;
        float c = (float)(g_cnt[g] > 0 ? g_cnt[g] : 1);
        out[i] = g_pool[i] / c;
    }
}

// ---------------- launcher ----------------
extern "C" void kernel_launch(void* const* d_in, const int* in_sizes, int n_in,
                              void* d_out, int out_size)
{
    const float* x     = (const float*)d_in[0];
    const int*   ei    = (const int*)d_in[1];
    const int*   batch = (const int*)d_in[2];
    const float *wA[3], *bA[3], *wB[3], *bB[3], *gam[3], *bet[3];
    for (int l = 0; l < 3; l++) {
        wA[l]  = (const float*)d_in[3 + 6*l + 0];
        bA[l]  = (const float*)d_in[3 + 6*l + 1];
        wB[l]  = (const float*)d_in[3 + 6*l + 2];
        bB[l]  = (const float*)d_in[3 + 6*l + 3];
        gam[l] = (const float*)d_in[3 + 6*l + 4];
        bet[l] = (const float*)d_in[3 + 6*l + 5];
    }
    const int* src = ei;
    const int* dst = ei + NE;

    float *h1, *h2;
    unsigned char *whi, *wlo;
    cudaGetSymbolAddress((void**)&h1,   g_h1);
    cudaGetSymbolAddress((void**)&h2,   g_h2);
    cudaGetSymbolAddress((void**)&whi,  g_whi);
    cudaGetSymbolAddress((void**)&wlo,  g_wlo);

    constexpr int SMF128 = 65536 + 65536 + 65536;  // 196608
    constexpr int SMF64  = 65536 + 65536 + 32768;  // 163840
    cudaFuncSetAttribute(gin_layer<128, false>, cudaFuncAttributeMaxDynamicSharedMemorySize, SMF128);
    cudaFuncSetAttribute(gin_layer<128, true >, cudaFuncAttributeMaxDynamicSharedMemorySize, SMF128);
    cudaFuncSetAttribute(gin_layer<64,  true >, cudaFuncAttributeMaxDynamicSharedMemorySize, SMF64);

    const int GB = (NN + 127) / 128;   // 782
    const int EG = (NE + 255) / 256;
    const int SG = (NN + 511) / 512;

    // ---- CSR build ----
    hist_kernel<<<EG, 256>>>(dst);
    scan_pass1<<<NBLK, 256>>>();
    scan_pass2<<<1, 64>>>();
    scan_pass3<<<NBLK, 256>>>();
    fill_kernel<<<EG, 256>>>(src, dst);

    // ---- W preconvert (+ pool/cnt zeroing) ----
    wconv_kernel<<<(5*16384 + 8192 + 255)/256, 256>>>(wA[0], wB[0], wA[1], wB[1], wA[2], wB[2]);

    // ---- layer 0 (fused gather + MLP) ----
    gin_layer<128, false><<<GB, 256, SMF128>>>(x, whi + 0*32768, wlo + 0*32768, bA[0],
                                               whi + 1*32768, wlo + 1*32768, bB[0], h1);
    stats_kernel<128><<<SG, 256>>>(h1);
    bn_finalize_kernel<<<1, 128>>>(gam[0], bet[0], 128);

    // ---- layer 1 ----
    gin_layer<128, true ><<<GB, 256, SMF128>>>(h1, whi + 2*32768, wlo + 2*32768, bA[1],
                                               whi + 3*32768, wlo + 3*32768, bB[1], h2);
    stats_kernel<128><<<SG, 256>>>(h2);
    bn_finalize_kernel<<<1, 128>>>(gam[1], bet[1], 128);

    // ---- layer 2 ----
    gin_layer<64, true ><<<GB, 256, SMF64>>>(h2, whi + 4*32768, wlo + 4*32768, bA[2],
                                             whi + 5*32768, wlo + 5*32768, bB[2], h1);
    stats_kernel<64><<<SG, 256>>>(h1);
    bn_finalize_kernel<<<1, 64>>>(gam[2], bet[2], 64);

    // ---- global mean pool (BN+ReLU fused) ----
    pool_sum_kernel<<<(NN * 16 + 255)/256, 256>>>(h1, batch);
    pool_cnt_kernel<<<296, 256>>>(batch);
    pool_fin_kernel<<<(NGR * DO_ + 255)/256, 256>>>((float*)d_out);
}

// round 11
// speedup vs baseline: 1.4102x; 1.4102x over previous
#include <cuda_runtime.h>
#include <cuda_bf16.h>
#include <cstdint>

#define NN   100000
#define NE   1600000
#define NGR  128
#define D_   128
#define DO_  64
#define BN_EPS 1e-5f
#define SCAN_ELEMS 2048
#define NBLK ((NN + SCAN_ELEMS - 1) / SCAN_ELEMS)   // 49

typedef unsigned long long ull;

// ---------------- scratch ----------------
__device__ __align__(16) float g_agg[(size_t)NN * D_];
__device__ __align__(16) float g_h1 [(size_t)NN * D_];
__device__ __align__(16) float g_h2 [(size_t)NN * D_];
__device__ __align__(16) __nv_bfloat16 g_hb[(size_t)NN * D_];   // bf16 copy of pre-BN h
__device__ __align__(16) float g_bnstats[2 * D_];
__device__ __align__(16) float g_scale[D_];
__device__ __align__(16) float g_shift[D_];
__device__ __align__(16) float g_pool[NGR * DO_];
__device__ __align__(16) int   g_cnt[NGR];
// CSR scratch
__device__ __align__(16) int g_deg[NN];
__device__ __align__(16) int g_off[NN + 1];
__device__ __align__(16) int g_cur[NN];
__device__ __align__(16) int g_csr[NE];
__device__ int g_bsum[64];
__device__ int g_bscan[64];
// pre-split, pre-swizzled W images
__device__ __align__(16) unsigned char g_whi[6 * 32768];
__device__ __align__(16) unsigned char g_wlo[6 * 32768];

// ---------------- asm helpers ----------------
__device__ __forceinline__ uint32_t smem_u32(const void* p) {
    uint32_t a;
    asm("{ .reg .u64 t; cvta.to.shared.u64 t, %1; cvt.u32.u64 %0, t; }" : "=r"(a) : "l"(p));
    return a;
}
__device__ __forceinline__ void ldsm_x4(uint32_t& r0, uint32_t& r1, uint32_t& r2, uint32_t& r3,
                                        uint32_t addr) {
    asm volatile("ldmatrix.sync.aligned.m8n8.x4.shared.b16 {%0,%1,%2,%3}, [%4];"
                 : "=r"(r0), "=r"(r1), "=r"(r2), "=r"(r3) : "r"(addr));
}
__device__ __forceinline__ void ldsm_x4t(uint32_t& r0, uint32_t& r1, uint32_t& r2, uint32_t& r3,
                                         uint32_t addr) {
    asm volatile("ldmatrix.sync.aligned.m8n8.x4.trans.shared.b16 {%0,%1,%2,%3}, [%4];"
                 : "=r"(r0), "=r"(r1), "=r"(r2), "=r"(r3) : "r"(addr));
}
__device__ __forceinline__ void mma16816(float* c, uint32_t a0, uint32_t a1, uint32_t a2,
                                         uint32_t a3, uint32_t b0, uint32_t b1) {
    asm volatile("mma.sync.aligned.m16n8k16.row.col.f32.bf16.bf16.f32 "
                 "{%0,%1,%2,%3}, {%4,%5,%6,%7}, {%8,%9}, {%0,%1,%2,%3};"
                 : "+f"(c[0]), "+f"(c[1]), "+f"(c[2]), "+f"(c[3])
                 : "r"(a0), "r"(a1), "r"(a2), "r"(a3), "r"(b0), "r"(b1));
}

// ---------------- CSR build ----------------
__global__ void hist_kernel(const int* __restrict__ dst) {
    int i = blockIdx.x * blockDim.x + threadIdx.x;
    if (i < NE) atomicAdd(&g_deg[__ldg(dst + i)], 1);
}
__global__ void scan_pass1() {
    __shared__ int ssum[8];
    int b = blockIdx.x, tid = threadIdx.x;
    int base = b * SCAN_ELEMS + tid * 8;
    int s = 0;
    #pragma unroll
    for (int j = 0; j < 8; j++) { int idx = base + j; s += (idx < NN) ? g_deg[idx] : 0; }
    #pragma unroll
    for (int o = 16; o; o >>= 1) s += __shfl_down_sync(0xffffffffu, s, o);
    if ((tid & 31) == 0) ssum[tid >> 5] = s;
    __syncthreads();
    if (tid == 0) {
        int t = 0;
        #pragma unroll
        for (int i = 0; i < 8; i++) t += ssum[i];
        g_bsum[b] = t;
    }
}
__global__ void scan_pass2() {
    int tid = threadIdx.x;
    int v = (tid < NBLK) ? g_bsum[tid] : 0;
    int incl = v, lane = tid & 31;
    #pragma unroll
    for (int o = 1; o < 32; o <<= 1) {
        int y = __shfl_up_sync(0xffffffffu, incl, o);
        if (lane >= o) incl += y;
    }
    __shared__ int w0;
    if (tid == 31) w0 = incl;
    __syncthreads();
    if (tid >= 32) incl += w0;
    if (tid < 64) g_bscan[tid] = incl - v;
    if (tid == 0) g_off[NN] = NE;
}
__global__ void scan_pass3() {
    int b = blockIdx.x, tid = threadIdx.x;
    int base = b * SCAN_ELEMS + tid * 8;
    int vals[8], t = 0;
    #pragma unroll
    for (int j = 0; j < 8; j++) { vals[j] = (base + j < NN) ? g_deg[base + j] : 0; t += vals[j]; }
    int lane = tid & 31, wid = tid >> 5, incl = t;
    #pragma unroll
    for (int o = 1; o < 32; o <<= 1) {
        int y = __shfl_up_sync(0xffffffffu, incl, o);
        if (lane >= o) incl += y;
    }
    __shared__ int wsum[8], woff[8];
    if (lane == 31) wsum[wid] = incl;
    __syncthreads();
    if (tid == 0) { int a = 0; for (int i = 0; i < 8; i++) { woff[i] = a; a += wsum[i]; } }
    __syncthreads();
    int run = g_bscan[b] + woff[wid] + (incl - t);
    #pragma unroll
    for (int j = 0; j < 8; j++) {
        int idx = base + j;
        if (idx < NN) {
            g_off[idx] = run; g_cur[idx] = run; run += vals[j];
            g_deg[idx] = 0;
        }
    }
}
__global__ void fill_kernel(const int* __restrict__ src, const int* __restrict__ dst) {
    int i = blockIdx.x * blockDim.x + threadIdx.x;
    if (i < NE) {
        int d = __ldg(dst + i);
        int p = atomicAdd(&g_cur[d], 1);
        g_csr[p] = __ldg(src + i);
    }
}

// ---------------- W split + swizzle preconvert (+ pool/cnt zeroing) ----------------
__global__ void wconv_kernel(const float* w0, const float* w1, const float* w2,
                             const float* w3, const float* w4, const float* w5)
{
    int i = blockIdx.x * blockDim.x + threadIdx.x;
    if (i < NGR * DO_) g_pool[i] = 0.f;
    if (i < NGR) g_cnt[i] = 0;
    if (i >= 5 * 16384 + 8192) return;
    int seg = i >> 14;
    int t = i & 16383;
    int nout = (seg == 5) ? 64 : 128;
    const float* W = (seg == 0) ? w0 : (seg == 1) ? w1 : (seg == 2) ? w2
                   : (seg == 3) ? w3 : (seg == 4) ? w4 : w5;
    int k = t / nout, n = t % nout;
    float w = __ldg(W + k * nout + n);
    __nv_bfloat16 hi = __float2bfloat16(w);
    __nv_bfloat16 lo = __float2bfloat16(w - __bfloat162float(hi));
    int pos = k * nout + ((((n >> 3) ^ (k & 7)) << 3) | (n & 7));
    ((__nv_bfloat16*)(g_whi + seg * 32768))[pos] = hi;
    ((__nv_bfloat16*)(g_wlo + seg * 32768))[pos] = lo;
}

// ---------------- helpers ----------------
__device__ __forceinline__ float4 bn_ap(float4 v, float4 sc, float4 sh, bool bn) {
    if (bn) {
        v.x = fmaxf(fmaf(v.x, sc.x, sh.x), 0.f);
        v.y = fmaxf(fmaf(v.y, sc.y, sh.y), 0.f);
        v.z = fmaxf(fmaf(v.z, sc.z, sh.z), 0.f);
        v.w = fmaxf(fmaf(v.w, sc.w, sh.w), 0.f);
    }
    return v;
}
__device__ __forceinline__ void f4acc(float4& a, float4 b) {
    a.x += b.x; a.y += b.y; a.z += b.z; a.w += b.w;
}
__device__ __forceinline__ float4 cvt_bf4(uint2 r) {
    __nv_bfloat162 a = *(__nv_bfloat162*)&r.x;
    __nv_bfloat162 b = *(__nv_bfloat162*)&r.y;
    return make_float4(__bfloat162float(a.x), __bfloat162float(a.y),
                       __bfloat162float(b.x), __bfloat162float(b.y));
}

// ---------------- gather fp32 (layer 0, identity f) — R4/R9 proven ----------------
__global__ void gather_f32_kernel(const float* __restrict__ h, float* __restrict__ out)
{
    int n = blockIdx.x * 8 + (threadIdx.x >> 5);
    if (n >= NN) return;
    int lane = threadIdx.x & 31;
    const float4* __restrict__ h4 = (const float4*)h;

    float4 a0 = __ldg(&h4[(size_t)n * 32 + lane]);
    float4 a1 = make_float4(0,0,0,0), a2 = make_float4(0,0,0,0), a3 = make_float4(0,0,0,0);

    int j = g_off[n], e1 = g_off[n + 1];
    for (; j + 4 <= e1; j += 4) {
        int i0 = __ldg(&g_csr[j]);
        int i1 = __ldg(&g_csr[j + 1]);
        int i2 = __ldg(&g_csr[j + 2]);
        int i3 = __ldg(&g_csr[j + 3]);
        float4 w0 = __ldg(&h4[(size_t)i0 * 32 + lane]);
        float4 w1 = __ldg(&h4[(size_t)i1 * 32 + lane]);
        float4 w2 = __ldg(&h4[(size_t)i2 * 32 + lane]);
        float4 w3 = __ldg(&h4[(size_t)i3 * 32 + lane]);
        f4acc(a0, w0); f4acc(a1, w1); f4acc(a2, w2); f4acc(a3, w3);
    }
    for (; j < e1; j++) {
        int s = __ldg(&g_csr[j]);
        f4acc(a0, __ldg(&h4[(size_t)s * 32 + lane]));
    }
    f4acc(a0, a1); f4acc(a2, a3); f4acc(a0, a2);
    ((float4*)out)[(size_t)n * 32 + lane] = a0;
}

// ---------------- gather bf16 (layers 1,2; BN+ReLU on the fly) — half the traffic ----
__global__ void gather_bf16_kernel(float* __restrict__ out)
{
    int n = blockIdx.x * 8 + (threadIdx.x >> 5);
    if (n >= NN) return;
    int lane = threadIdx.x & 31;
    const uint2* __restrict__ hb = (const uint2*)g_hb;

    float4 sc = *(const float4*)(g_scale + lane * 4);
    float4 sh = *(const float4*)(g_shift + lane * 4);

    float4 a0 = bn_ap(cvt_bf4(__ldg(&hb[(size_t)n * 32 + lane])), sc, sh, true);
    float4 a1 = make_float4(0,0,0,0), a2 = make_float4(0,0,0,0), a3 = make_float4(0,0,0,0);

    int j = g_off[n], e1 = g_off[n + 1];
    for (; j + 4 <= e1; j += 4) {
        int i0 = __ldg(&g_csr[j]);
        int i1 = __ldg(&g_csr[j + 1]);
        int i2 = __ldg(&g_csr[j + 2]);
        int i3 = __ldg(&g_csr[j + 3]);
        uint2 w0 = __ldg(&hb[(size_t)i0 * 32 + lane]);
        uint2 w1 = __ldg(&hb[(size_t)i1 * 32 + lane]);
        uint2 w2 = __ldg(&hb[(size_t)i2 * 32 + lane]);
        uint2 w3 = __ldg(&hb[(size_t)i3 * 32 + lane]);
        f4acc(a0, bn_ap(cvt_bf4(w0), sc, sh, true));
        f4acc(a1, bn_ap(cvt_bf4(w1), sc, sh, true));
        f4acc(a2, bn_ap(cvt_bf4(w2), sc, sh, true));
        f4acc(a3, bn_ap(cvt_bf4(w3), sc, sh, true));
    }
    for (; j < e1; j++) {
        int s = __ldg(&g_csr[j]);
        f4acc(a0, bn_ap(cvt_bf4(__ldg(&hb[(size_t)s * 32 + lane])), sc, sh, true));
    }
    f4acc(a0, a1); f4acc(a2, a3); f4acc(a0, a2);
    ((float4*)out)[(size_t)n * 32 + lane] = a0;
}

// ---------------- mma_loop ----------------
template<int NT>
__device__ __forceinline__ void mma_loop(uint32_t sb, uint32_t aHi, uint32_t aLo,
                                         uint32_t bHi, uint32_t bLo,
                                         int wid, int lane, float acc[][4])
{
    const int la = lane & 15;
    const int lb = lane >> 4;
    const int l7 = lane & 7;
    const int BR = NT * 16;
    const uint32_t aRow = (uint32_t)((wid * 16 + la) * 256);
    const uint32_t bRow = (uint32_t)(la * BR);
    #pragma unroll 2
    for (int k0 = 0; k0 < 128; k0 += 16) {
        uint32_t kc = (uint32_t)((k0 >> 3) + lb);
        uint32_t aoff = aRow + ((kc ^ (uint32_t)l7) << 4);
        uint32_t ah0, ah1, ah2, ah3, al0, al1, al2, al3;
        ldsm_x4(ah0, ah1, ah2, ah3, sb + aHi + aoff);
        ldsm_x4(al0, al1, al2, al3, sb + aLo + aoff);
        uint32_t bbase = (uint32_t)(k0 * BR) + bRow;
        #pragma unroll
        for (int nt = 0; nt < NT; nt += 2) {
            uint32_t boff = bbase + ((((uint32_t)(nt + lb)) ^ (uint32_t)l7) << 4);
            uint32_t bh0, bh1, bh2, bh3, bl0, bl1, bl2, bl3;
            ldsm_x4t(bh0, bh1, bh2, bh3, sb + bHi + boff);
            ldsm_x4t(bl0, bl1, bl2, bl3, sb + bLo + boff);
            mma16816(acc[nt],     ah0, ah1, ah2, ah3, bh0, bh1);
            mma16816(acc[nt + 1], ah0, ah1, ah2, ah3, bh2, bh3);
            mma16816(acc[nt],     ah0, ah1, ah2, ah3, bl0, bl1);
            mma16816(acc[nt + 1], ah0, ah1, ah2, ah3, bl2, bl3);
            mma16816(acc[nt],     al0, al1, al2, al3, bh0, bh1);
            mma16816(acc[nt + 1], al0, al1, al2, al3, bh2, bh3);
        }
    }
}

// ---------------- fused 2-GEMM MLP (R9-proven) + optional bf16 copy-out ----------------
template<int NOUT, bool WB16>
__global__ __launch_bounds__(256, 1)
void mlp_mma(const float* __restrict__ A,
             const unsigned char* __restrict__ w1h, const unsigned char* __restrict__ w1l,
             const float* __restrict__ b1,
             const unsigned char* __restrict__ w2h, const unsigned char* __restrict__ w2l,
             const float* __restrict__ b2, float* __restrict__ out)
{
    constexpr int NT2  = NOUT / 8;
    constexpr int AHI  = 0;
    constexpr int ALO  = 32768;
    constexpr int B1HI = 65536;
    constexpr int B1LO = 98304;
    constexpr int B2HI = 131072;
    constexpr int B2LO = 131072 + NOUT * 256;

    extern __shared__ __align__(16) char smem[];
    const uint32_t sb = smem_u32(smem);
    const int tid  = threadIdx.x;
    const int wid  = tid >> 5;
    const int lane = tid & 31;
    const int row0 = blockIdx.x * 128;

    // B tiles
    {
        const float4* s1 = (const float4*)w1h;
        const float4* s2 = (const float4*)w1l;
        float4* d1 = (float4*)(smem + B1HI);
        float4* d2 = (float4*)(smem + B1LO);
        #pragma unroll
        for (int i = tid; i < 2048; i += 256) { d1[i] = s1[i]; d2[i] = s2[i]; }
        const float4* s3 = (const float4*)w2h;
        const float4* s4 = (const float4*)w2l;
        float4* d3 = (float4*)(smem + B2HI);
        float4* d4 = (float4*)(smem + B2LO);
        #pragma unroll
        for (int i = tid; i < NOUT * 16; i += 256) { d3[i] = s3[i]; d4[i] = s4[i]; }
    }
    // A tile: fp32 -> bf16 hi/lo, swizzled
    for (int i = tid; i < 2048; i += 256) {
        int r = i >> 4, c = i & 15;
        int gr = row0 + r;
        float4 v0 = make_float4(0,0,0,0), v1 = make_float4(0,0,0,0);
        if (gr < NN) {
            const float4* ap = (const float4*)(A + (size_t)gr * 128 + c * 8);
            v0 = __ldg(ap); v1 = __ldg(ap + 1);
        }
        float vv[8] = {v0.x, v0.y, v0.z, v0.w, v1.x, v1.y, v1.z, v1.w};
        uint4 hq, lq;
        uint32_t* hp = (uint32_t*)&hq;
        uint32_t* lp = (uint32_t*)&lq;
        #pragma unroll
        for (int p = 0; p < 4; p++) {
            __nv_bfloat162 h2, l2;
            h2.x = __float2bfloat16(vv[2*p]);
            h2.y = __float2bfloat16(vv[2*p+1]);
            l2.x = __float2bfloat16(vv[2*p]   - __bfloat162float(h2.x));
            l2.y = __float2bfloat16(vv[2*p+1] - __bfloat162float(h2.y));
            hp[p] = *(uint32_t*)&h2;
            lp[p] = *(uint32_t*)&l2;
        }
        uint32_t off = (uint32_t)(r * 256 + ((c ^ (r & 7)) << 4));
        *(uint4*)(smem + AHI + off) = hq;
        *(uint4*)(smem + ALO + off) = lq;
    }
    __syncthreads();

    // stage 1
    float acc[16][4];
    #pragma unroll
    for (int t = 0; t < 16; t++)
        #pragma unroll
        for (int e = 0; e < 4; e++) acc[t][e] = 0.f;
    mma_loop<16>(sb, AHI, ALO, B1HI, B1LO, wid, lane, acc);
    __syncthreads();

    // epilogue 1
    {
        int rr1 = wid * 16 + (lane >> 2);
        int rr2 = rr1 + 8;
        uint32_t cb1 = (uint32_t)(rr1 * 256);
        uint32_t cb2 = (uint32_t)(rr2 * 256);
        int sw1 = (rr1 & 7), sw2 = (rr2 & 7);
        int cpos = (lane & 3) * 4;
        #pragma unroll
        for (int nt = 0; nt < 16; nt++) {
            int col = nt * 8 + (lane & 3) * 2;
            float2 bb = __ldg((const float2*)(b1 + col));
            float v0 = fmaxf(acc[nt][0] + bb.x, 0.f);
            float v1 = fmaxf(acc[nt][1] + bb.y, 0.f);
            float v2 = fmaxf(acc[nt][2] + bb.x, 0.f);
            float v3 = fmaxf(acc[nt][3] + bb.y, 0.f);
            __nv_bfloat162 h2, l2;
            h2.x = __float2bfloat16(v0);
            h2.y = __float2bfloat16(v1);
            l2.x = __float2bfloat16(v0 - __bfloat162float(h2.x));
            l2.y = __float2bfloat16(v1 - __bfloat162float(h2.y));
            uint32_t o1 = cb1 + ((uint32_t)(nt ^ sw1) << 4) + cpos;
            *(uint32_t*)(smem + AHI + o1) = *(uint32_t*)&h2;
            *(uint32_t*)(smem + ALO + o1) = *(uint32_t*)&l2;
            h2.x = __float2bfloat16(v2);
            h2.y = __float2bfloat16(v3);
            l2.x = __float2bfloat16(v2 - __bfloat162float(h2.x));
            l2.y = __float2bfloat16(v3 - __bfloat162float(h2.y));
            uint32_t o2 = cb2 + ((uint32_t)(nt ^ sw2) << 4) + cpos;
            *(uint32_t*)(smem + AHI + o2) = *(uint32_t*)&h2;
            *(uint32_t*)(smem + ALO + o2) = *(uint32_t*)&l2;
        }
    }
    __syncthreads();

    // stage 2
    float acc2[NT2][4];
    #pragma unroll
    for (int t = 0; t < NT2; t++)
        #pragma unroll
        for (int e = 0; e < 4; e++) acc2[t][e] = 0.f;
    mma_loop<NT2>(sb, AHI, ALO, B2HI, B2LO, wid, lane, acc2);

    int r1 = row0 + wid * 16 + (lane >> 2);
    int r2 = r1 + 8;
    #pragma unroll
    for (int nt = 0; nt < NT2; nt++) {
        int col = nt * 8 + (lane & 3) * 2;
        float2 bb = __ldg((const float2*)(b2 + col));
        float v0 = acc2[nt][0] + bb.x;
        float v1 = acc2[nt][1] + bb.y;
        float v2 = acc2[nt][2] + bb.x;
        float v3 = acc2[nt][3] + bb.y;
        if (r1 < NN) {
            *(float2*)(out + (size_t)r1 * NOUT + col) = make_float2(v0, v1);
            if (WB16) {
                __nv_bfloat162 p;
                p.x = __float2bfloat16(v0); p.y = __float2bfloat16(v1);
                *(__nv_bfloat162*)(g_hb + (size_t)r1 * 128 + col) = p;
            }
        }
        if (r2 < NN) {
            *(float2*)(out + (size_t)r2 * NOUT + col) = make_float2(v2, v3);
            if (WB16) {
                __nv_bfloat162 p;
                p.x = __float2bfloat16(v2); p.y = __float2bfloat16(v3);
                *(__nv_bfloat162*)(g_hb + (size_t)r2 * 128 + col) = p;
            }
        }
    }
}

// ---------------- BN column stats ----------------
template<int NOUT>
__global__ void stats_kernel(const float* __restrict__ h)
{
    constexpr int QC = NOUT / 4;
    constexpr int STEP = 256 / QC;
    __shared__ float ss[NOUT], sq[NOUT];
    int tid = threadIdx.x;
    if (tid < NOUT) { ss[tid] = 0.f; sq[tid] = 0.f; }
    __syncthreads();
    int qc = tid % QC, rg = tid / QC;
    int rend = min(blockIdx.x * 512 + 512, NN);
    float4 s4 = make_float4(0,0,0,0), q4 = make_float4(0,0,0,0);
    for (int r = blockIdx.x * 512 + rg; r < rend; r += STEP) {
        float4 v = __ldg((const float4*)(h + (size_t)r * NOUT) + qc);
        s4.x += v.x; s4.y += v.y; s4.z += v.z; s4.w += v.w;
        q4.x += v.x*v.x; q4.y += v.y*v.y; q4.z += v.z*v.z; q4.w += v.w*v.w;
    }
    int c = qc * 4;
    atomicAdd(&ss[c+0], s4.x); atomicAdd(&ss[c+1], s4.y);
    atomicAdd(&ss[c+2], s4.z); atomicAdd(&ss[c+3], s4.w);
    atomicAdd(&sq[c+0], q4.x); atomicAdd(&sq[c+1], q4.y);
    atomicAdd(&sq[c+2], q4.z); atomicAdd(&sq[c+3], q4.w);
    __syncthreads();
    if (tid < NOUT) {
        atomicAdd(&g_bnstats[tid], ss[tid]);
        atomicAdd(&g_bnstats[NOUT + tid], sq[tid]);
    }
}

// ---------------- BN finalize (resets stats after read) ----------------
__global__ void bn_finalize_kernel(const float* __restrict__ gamma,
                                   const float* __restrict__ beta, int nout)
{
    int c = threadIdx.x;
    if (c < nout) {
        const float invN = 1.0f / (float)NN;
        float sv = g_bnstats[c];
        float qv = g_bnstats[nout + c];
        float mu  = sv * invN;
        float var = qv * invN - mu * mu;
        float s   = gamma[c] * rsqrtf(var + BN_EPS);
        g_scale[c] = s;
        g_shift[c] = beta[c] - mu * s;
        g_bnstats[c] = 0.f;
        g_bnstats[nout + c] = 0.f;
    }
}

// ---------------- pooling (BN+ReLU fused) ----------------
__global__ void pool_sum_kernel(const float* __restrict__ pre, const int* __restrict__ batch)
{
    int t = blockIdx.x * blockDim.x + threadIdx.x;
    if (t >= NN * 16) return;
    int n = t >> 4, q = t & 15;
    int c = q << 2;
    int b = __ldg(batch + n);
    float4 v  = *(const float4*)(pre + (size_t)n * DO_ + c);
    float4 sc = *(const float4*)(g_scale + c);
    float4 sh = *(const float4*)(g_shift + c);
    v.x = fmaxf(fmaf(v.x, sc.x, sh.x), 0.f);
    v.y = fmaxf(fmaf(v.y, sc.y, sh.y), 0.f);
    v.z = fmaxf(fmaf(v.z, sc.z, sh.z), 0.f);
    v.w = fmaxf(fmaf(v.w, sc.w, sh.w), 0.f);
    float* p = g_pool + b * DO_ + c;
    asm volatile("red.global.add.v4.f32 [%0], {%1, %2, %3, %4};"
                 :: "l"(p), "f"(v.x), "f"(v.y), "f"(v.z), "f"(v.w) : "memory");
}

__global__ void pool_cnt_kernel(const int* __restrict__ batch)
{
    __shared__ int sc[NGR];
    for (int i = threadIdx.x; i < NGR; i += blockDim.x) sc[i] = 0;
    __syncthreads();
    for (int i = blockIdx.x * blockDim.x + threadIdx.x; i < NN; i += gridDim.x * blockDim.x)
        atomicAdd(&sc[__ldg(batch + i)], 1);
    __syncthreads();
    for (int i = threadIdx.x; i < NGR; i += blockDim.x)
        if (sc[i]) atomicAdd(&g_cnt[i], sc[i]);
}

__global__ void pool_fin_kernel(float* __restrict__ out)
{
    int i = blockIdx.x * blockDim.x + threadIdx.x;
    if (i < NGR * DO_) {
        int g = i >> 6;
        float c = (float)(g_cnt[g] > 0 ? g_cnt[g] : 1);
        out[i] = g_pool[i] / c;
    }
}

// ---------------- launcher ----------------
extern "C" void kernel_launch(void* const* d_in, const int* in_sizes, int n_in,
                              void* d_out, int out_size)
{
    const float* x     = (const float*)d_in[0];
    const int*   ei    = (const int*)d_in[1];
    const int*   batch = (const int*)d_in[2];
    const float *wA[3], *bA[3], *wB[3], *bB[3], *gam[3], *bet[3];
    for (int l = 0; l < 3; l++) {
        wA[l]  = (const float*)d_in[3 + 6*l + 0];
        bA[l]  = (const float*)d_in[3 + 6*l + 1];
        wB[l]  = (const float*)d_in[3 + 6*l + 2];
        bB[l]  = (const float*)d_in[3 + 6*l + 3];
        gam[l] = (const float*)d_in[3 + 6*l + 4];
        bet[l] = (const float*)d_in[3 + 6*l + 5];
    }
    const int* src = ei;
    const int* dst = ei + NE;

    float *agg, *h1, *h2;
    unsigned char *whi, *wlo;
    cudaGetSymbolAddress((void**)&agg,  g_agg);
    cudaGetSymbolAddress((void**)&h1,   g_h1);
    cudaGetSymbolAddress((void**)&h2,   g_h2);
    cudaGetSymbolAddress((void**)&whi,  g_whi);
    cudaGetSymbolAddress((void**)&wlo,  g_wlo);

    constexpr int SMF128 = 65536 + 65536 + 65536;  // 196608
    constexpr int SMF64  = 65536 + 65536 + 32768;  // 163840
    cudaFuncSetAttribute(mlp_mma<128, true >, cudaFuncAttributeMaxDynamicSharedMemorySize, SMF128);
    cudaFuncSetAttribute(mlp_mma<64,  false>, cudaFuncAttributeMaxDynamicSharedMemorySize, SMF64);

    const int GB = (NN + 127) / 128;   // 782
    const int EG = (NE + 255) / 256;
    const int GG = (NN + 7) / 8;
    const int SG = (NN + 511) / 512;

    // ---- CSR build ----
    hist_kernel<<<EG, 256>>>(dst);
    scan_pass1<<<NBLK, 256>>>();
    scan_pass2<<<1, 64>>>();
    scan_pass3<<<NBLK, 256>>>();
    fill_kernel<<<EG, 256>>>(src, dst);

    // ---- W preconvert (+ pool/cnt zeroing) ----
    wconv_kernel<<<(5*16384 + 8192 + 255)/256, 256>>>(wA[0], wB[0], wA[1], wB[1], wA[2], wB[2]);

    // ---- layer 0 (fp32 gather of x; MLP also emits bf16 copy of h1) ----
    gather_f32_kernel<<<GG, 256>>>(x, agg);
    mlp_mma<128, true><<<GB, 256, SMF128>>>(agg, whi + 0*32768, wlo + 0*32768, bA[0],
                                            whi + 1*32768, wlo + 1*32768, bB[0], h1);
    stats_kernel<128><<<SG, 256>>>(h1);
    bn_finalize_kernel<<<1, 128>>>(gam[0], bet[0], 128);

    // ---- layer 1 (bf16 gather; MLP emits bf16 copy of h2) ----
    gather_bf16_kernel<<<GG, 256>>>(agg);
    mlp_mma<128, true><<<GB, 256, SMF128>>>(agg, whi + 2*32768, wlo + 2*32768, bA[1],
                                            whi + 3*32768, wlo + 3*32768, bB[1], h2);
    stats_kernel<128><<<SG, 256>>>(h2);
    bn_finalize_kernel<<<1, 128>>>(gam[1], bet[1], 128);

    // ---- layer 2 (bf16 gather; no copy-out) ----
    gather_bf16_kernel<<<GG, 256>>>(agg);
    mlp_mma<64, false><<<GB, 256, SMF64>>>(agg, whi + 4*32768, wlo + 4*32768, bA[2],
                                           whi + 5*32768, wlo + 5*32768, bB[2], h1);
    stats_kernel<64><<<SG, 256>>>(h1);
    bn_finalize_kernel<<<1, 64>>>(gam[2], bet[2], 64);

    // ---- global mean pool (BN+ReLU fused) ----
    pool_sum_kernel<<<(NN * 16 + 255)/256, 256>>>(h1, batch);
    pool_cnt_kernel<<<296, 256>>>(batch);
    pool_fin_kernel<<<(NGR * DO_ + 255)/256, 256>>>((float*)d_out);
}

// round 12
// speedup vs baseline: 1.4999x; 1.0636x over previous
#include <cuda_runtime.h>
#include <cuda_bf16.h>
#include <cstdint>

#define NN   100000
#define NE   1600000
#define NGR  128
#define D_   128
#define DO_  64
#define BN_EPS 1e-5f
#define SCAN_ELEMS 2048
#define NBLK ((NN + SCAN_ELEMS - 1) / SCAN_ELEMS)   // 49

typedef unsigned long long ull;

// ---------------- scratch ----------------
__device__ __align__(16) float g_agg[(size_t)NN * D_];
__device__ __align__(16) float g_h1 [(size_t)NN * D_];
__device__ __align__(16) float g_h2 [(size_t)NN * D_];
__device__ __align__(16) float g_hbn[(size_t)NN * D_];   // BN+ReLU-applied h
__device__ __align__(16) float g_bnstats[2 * D_];
__device__ __align__(16) float g_scale[D_];
__device__ __align__(16) float g_shift[D_];
__device__ __align__(16) float g_pool[NGR * DO_];
__device__ __align__(16) int   g_cnt[NGR];
// CSR scratch
__device__ __align__(16) int g_deg[NN];
__device__ __align__(16) int g_off[NN + 1];
__device__ __align__(16) int g_cur[NN];
__device__ __align__(16) int g_csr[NE];
__device__ int g_bsum[64];
__device__ int g_bscan[64];
// pre-split, pre-swizzled W images
__device__ __align__(16) unsigned char g_whi[6 * 32768];
__device__ __align__(16) unsigned char g_wlo[6 * 32768];

// ---------------- asm helpers ----------------
__device__ __forceinline__ uint32_t smem_u32(const void* p) {
    uint32_t a;
    asm("{ .reg .u64 t; cvta.to.shared.u64 t, %1; cvt.u32.u64 %0, t; }" : "=r"(a) : "l"(p));
    return a;
}
__device__ __forceinline__ ull add2(ull a, ull b) {
    ull r;
    asm("add.rn.f32x2 %0, %1, %2;" : "=l"(r) : "l"(a), "l"(b));
    return r;
}
__device__ __forceinline__ void ldsm_x4(uint32_t& r0, uint32_t& r1, uint32_t& r2, uint32_t& r3,
                                        uint32_t addr) {
    asm volatile("ldmatrix.sync.aligned.m8n8.x4.shared.b16 {%0,%1,%2,%3}, [%4];"
                 : "=r"(r0), "=r"(r1), "=r"(r2), "=r"(r3) : "r"(addr));
}
__device__ __forceinline__ void ldsm_x4t(uint32_t& r0, uint32_t& r1, uint32_t& r2, uint32_t& r3,
                                         uint32_t addr) {
    asm volatile("ldmatrix.sync.aligned.m8n8.x4.trans.shared.b16 {%0,%1,%2,%3}, [%4];"
                 : "=r"(r0), "=r"(r1), "=r"(r2), "=r"(r3) : "r"(addr));
}
__device__ __forceinline__ void mma16816(float* c, uint32_t a0, uint32_t a1, uint32_t a2,
                                         uint32_t a3, uint32_t b0, uint32_t b1) {
    asm volatile("mma.sync.aligned.m16n8k16.row.col.f32.bf16.bf16.f32 "
                 "{%0,%1,%2,%3}, {%4,%5,%6,%7}, {%8,%9}, {%0,%1,%2,%3};"
                 : "+f"(c[0]), "+f"(c[1]), "+f"(c[2]), "+f"(c[3])
                 : "r"(a0), "r"(a1), "r"(a2), "r"(a3), "r"(b0), "r"(b1));
}

// ---------------- CSR build ----------------
__global__ void hist_kernel(const int* __restrict__ dst) {
    int i = blockIdx.x * blockDim.x + threadIdx.x;
    if (i < NE) atomicAdd(&g_deg[__ldg(dst + i)], 1);
}
__global__ void scan_pass1() {
    __shared__ int ssum[8];
    int b = blockIdx.x, tid = threadIdx.x;
    int base = b * SCAN_ELEMS + tid * 8;
    int s = 0;
    #pragma unroll
    for (int j = 0; j < 8; j++) { int idx = base + j; s += (idx < NN) ? g_deg[idx] : 0; }
    #pragma unroll
    for (int o = 16; o; o >>= 1) s += __shfl_down_sync(0xffffffffu, s, o);
    if ((tid & 31) == 0) ssum[tid >> 5] = s;
    __syncthreads();
    if (tid == 0) {
        int t = 0;
        #pragma unroll
        for (int i = 0; i < 8; i++) t += ssum[i];
        g_bsum[b] = t;
    }
}
__global__ void scan_pass2() {
    int tid = threadIdx.x;
    int v = (tid < NBLK) ? g_bsum[tid] : 0;
    int incl = v, lane = tid & 31;
    #pragma unroll
    for (int o = 1; o < 32; o <<= 1) {
        int y = __shfl_up_sync(0xffffffffu, incl, o);
        if (lane >= o) incl += y;
    }
    __shared__ int w0;
    if (tid == 31) w0 = incl;
    __syncthreads();
    if (tid >= 32) incl += w0;
    if (tid < 64) g_bscan[tid] = incl - v;
    if (tid == 0) g_off[NN] = NE;
}
__global__ void scan_pass3() {
    int b = blockIdx.x, tid = threadIdx.x;
    int base = b * SCAN_ELEMS + tid * 8;
    int vals[8], t = 0;
    #pragma unroll
    for (int j = 0; j < 8; j++) { vals[j] = (base + j < NN) ? g_deg[base + j] : 0; t += vals[j]; }
    int lane = tid & 31, wid = tid >> 5, incl = t;
    #pragma unroll
    for (int o = 1; o < 32; o <<= 1) {
        int y = __shfl_up_sync(0xffffffffu, incl, o);
        if (lane >= o) incl += y;
    }
    __shared__ int wsum[8], woff[8];
    if (lane == 31) wsum[wid] = incl;
    __syncthreads();
    if (tid == 0) { int a = 0; for (int i = 0; i < 8; i++) { woff[i] = a; a += wsum[i]; } }
    __syncthreads();
    int run = g_bscan[b] + woff[wid] + (incl - t);
    #pragma unroll
    for (int j = 0; j < 8; j++) {
        int idx = base + j;
        if (idx < NN) {
            g_off[idx] = run; g_cur[idx] = run; run += vals[j];
            g_deg[idx] = 0;
        }
    }
}
__global__ void fill_kernel(const int* __restrict__ src, const int* __restrict__ dst) {
    int i = blockIdx.x * blockDim.x + threadIdx.x;
    if (i < NE) {
        int d = __ldg(dst + i);
        int p = atomicAdd(&g_cur[d], 1);
        g_csr[p] = __ldg(src + i);
    }
}

// ---------------- W split + swizzle preconvert (+ pool/cnt zeroing) ----------------
__global__ void wconv_kernel(const float* w0, const float* w1, const float* w2,
                             const float* w3, const float* w4, const float* w5)
{
    int i = blockIdx.x * blockDim.x + threadIdx.x;
    if (i < NGR * DO_) g_pool[i] = 0.f;
    if (i < NGR) g_cnt[i] = 0;
    if (i >= 5 * 16384 + 8192) return;
    int seg = i >> 14;
    int t = i & 16383;
    int nout = (seg == 5) ? 64 : 128;
    const float* W = (seg == 0) ? w0 : (seg == 1) ? w1 : (seg == 2) ? w2
                   : (seg == 3) ? w3 : (seg == 4) ? w4 : w5;
    int k = t / nout, n = t % nout;
    float w = __ldg(W + k * nout + n);
    __nv_bfloat16 hi = __float2bfloat16(w);
    __nv_bfloat16 lo = __float2bfloat16(w - __bfloat162float(hi));
    int pos = k * nout + ((((n >> 3) ^ (k & 7)) << 3) | (n & 7));
    ((__nv_bfloat16*)(g_whi + seg * 32768))[pos] = hi;
    ((__nv_bfloat16*)(g_wlo + seg * 32768))[pos] = lo;
}

// ---------------- pure-sum gather (f32x2 packed adds, no BN math) ----------------
__global__ void gather_kernel(const float* __restrict__ h, float* __restrict__ out)
{
    int n = blockIdx.x * 8 + (threadIdx.x >> 5);
    if (n >= NN) return;
    int lane = threadIdx.x & 31;
    const ulonglong2* __restrict__ h2 = (const ulonglong2*)h;

    ulonglong2 s = __ldg(&h2[(size_t)n * 32 + lane]);   // self term
    ull a0 = s.x, b0 = s.y;
    ull a1 = 0, b1 = 0, a2 = 0, b2 = 0, a3 = 0, b3 = 0;

    int j = g_off[n], e1 = g_off[n + 1];
    for (; j + 4 <= e1; j += 4) {
        int i0 = __ldg(&g_csr[j]);
        int i1 = __ldg(&g_csr[j + 1]);
        int i2 = __ldg(&g_csr[j + 2]);
        int i3 = __ldg(&g_csr[j + 3]);
        ulonglong2 w0 = __ldg(&h2[(size_t)i0 * 32 + lane]);
        ulonglong2 w1 = __ldg(&h2[(size_t)i1 * 32 + lane]);
        ulonglong2 w2 = __ldg(&h2[(size_t)i2 * 32 + lane]);
        ulonglong2 w3 = __ldg(&h2[(size_t)i3 * 32 + lane]);
        a0 = add2(a0, w0.x); b0 = add2(b0, w0.y);
        a1 = add2(a1, w1.x); b1 = add2(b1, w1.y);
        a2 = add2(a2, w2.x); b2 = add2(b2, w2.y);
        a3 = add2(a3, w3.x); b3 = add2(b3, w3.y);
    }
    for (; j < e1; j++) {
        int sidx = __ldg(&g_csr[j]);
        ulonglong2 w = __ldg(&h2[(size_t)sidx * 32 + lane]);
        a0 = add2(a0, w.x); b0 = add2(b0, w.y);
    }
    a0 = add2(add2(a0, a1), add2(a2, a3));
    b0 = add2(add2(b0, b1), add2(b2, b3));
    ulonglong2 r; r.x = a0; r.y = b0;
    ((ulonglong2*)out)[(size_t)n * 32 + lane] = r;
}

// ---------------- BN+ReLU apply: hbn = max(h*scale+shift, 0) ----------------
__global__ void bn_apply_kernel(const float* __restrict__ pre, float* __restrict__ outbn)
{
    int i = blockIdx.x * blockDim.x + threadIdx.x;
    if (i >= NN * 32) return;            // float4 units (d=128)
    int c = (i & 31) << 2;
    float4 v  = __ldg((const float4*)pre + i);
    float4 sc = *(const float4*)(g_scale + c);
    float4 sh = *(const float4*)(g_shift + c);
    v.x = fmaxf(fmaf(v.x, sc.x, sh.x), 0.f);
    v.y = fmaxf(fmaf(v.y, sc.y, sh.y), 0.f);
    v.z = fmaxf(fmaf(v.z, sc.z, sh.z), 0.f);
    v.w = fmaxf(fmaf(v.w, sc.w, sh.w), 0.f);
    ((float4*)outbn)[i] = v;
}

// ---------------- mma_loop ----------------
template<int NT>
__device__ __forceinline__ void mma_loop(uint32_t sb, uint32_t aHi, uint32_t aLo,
                                         uint32_t bHi, uint32_t bLo,
                                         int wid, int lane, float acc[][4])
{
    const int la = lane & 15;
    const int lb = lane >> 4;
    const int l7 = lane & 7;
    const int BR = NT * 16;
    const uint32_t aRow = (uint32_t)((wid * 16 + la) * 256);
    const uint32_t bRow = (uint32_t)(la * BR);
    #pragma unroll 2
    for (int k0 = 0; k0 < 128; k0 += 16) {
        uint32_t kc = (uint32_t)((k0 >> 3) + lb);
        uint32_t aoff = aRow + ((kc ^ (uint32_t)l7) << 4);
        uint32_t ah0, ah1, ah2, ah3, al0, al1, al2, al3;
        ldsm_x4(ah0, ah1, ah2, ah3, sb + aHi + aoff);
        ldsm_x4(al0, al1, al2, al3, sb + aLo + aoff);
        uint32_t bbase = (uint32_t)(k0 * BR) + bRow;
        #pragma unroll
        for (int nt = 0; nt < NT; nt += 2) {
            uint32_t boff = bbase + ((((uint32_t)(nt + lb)) ^ (uint32_t)l7) << 4);
            uint32_t bh0, bh1, bh2, bh3, bl0, bl1, bl2, bl3;
            ldsm_x4t(bh0, bh1, bh2, bh3, sb + bHi + boff);
            ldsm_x4t(bl0, bl1, bl2, bl3, sb + bLo + boff);
            mma16816(acc[nt],     ah0, ah1, ah2, ah3, bh0, bh1);
            mma16816(acc[nt + 1], ah0, ah1, ah2, ah3, bh2, bh3);
            mma16816(acc[nt],     ah0, ah1, ah2, ah3, bl0, bl1);
            mma16816(acc[nt + 1], ah0, ah1, ah2, ah3, bl2, bl3);
            mma16816(acc[nt],     al0, al1, al2, al3, bh0, bh1);
            mma16816(acc[nt + 1], al0, al1, al2, al3, bh2, bh3);
        }
    }
}

// ---------------- fused 2-GEMM MLP (R9-proven) ----------------
template<int NOUT>
__global__ __launch_bounds__(256, 1)
void mlp_mma(const float* __restrict__ A,
             const unsigned char* __restrict__ w1h, const unsigned char* __restrict__ w1l,
             const float* __restrict__ b1,
             const unsigned char* __restrict__ w2h, const unsigned char* __restrict__ w2l,
             const float* __restrict__ b2, float* __restrict__ out)
{
    constexpr int NT2  = NOUT / 8;
    constexpr int AHI  = 0;
    constexpr int ALO  = 32768;
    constexpr int B1HI = 65536;
    constexpr int B1LO = 98304;
    constexpr int B2HI = 131072;
    constexpr int B2LO = 131072 + NOUT * 256;

    extern __shared__ __align__(16) char smem[];
    const uint32_t sb = smem_u32(smem);
    const int tid  = threadIdx.x;
    const int wid  = tid >> 5;
    const int lane = tid & 31;
    const int row0 = blockIdx.x * 128;

    // B tiles
    {
        const float4* s1 = (const float4*)w1h;
        const float4* s2 = (const float4*)w1l;
        float4* d1 = (float4*)(smem + B1HI);
        float4* d2 = (float4*)(smem + B1LO);
        #pragma unroll
        for (int i = tid; i < 2048; i += 256) { d1[i] = s1[i]; d2[i] = s2[i]; }
        const float4* s3 = (const float4*)w2h;
        const float4* s4 = (const float4*)w2l;
        float4* d3 = (float4*)(smem + B2HI);
        float4* d4 = (float4*)(smem + B2LO);
        #pragma unroll
        for (int i = tid; i < NOUT * 16; i += 256) { d3[i] = s3[i]; d4[i] = s4[i]; }
    }
    // A tile: fp32 -> bf16 hi/lo, swizzled
    for (int i = tid; i < 2048; i += 256) {
        int r = i >> 4, c = i & 15;
        int gr = row0 + r;
        float4 v0 = make_float4(0,0,0,0), v1 = make_float4(0,0,0,0);
        if (gr < NN) {
            const float4* ap = (const float4*)(A + (size_t)gr * 128 + c * 8);
            v0 = __ldg(ap); v1 = __ldg(ap + 1);
        }
        float vv[8] = {v0.x, v0.y, v0.z, v0.w, v1.x, v1.y, v1.z, v1.w};
        uint4 hq, lq;
        uint32_t* hp = (uint32_t*)&hq;
        uint32_t* lp = (uint32_t*)&lq;
        #pragma unroll
        for (int p = 0; p < 4; p++) {
            __nv_bfloat162 h2, l2;
            h2.x = __float2bfloat16(vv[2*p]);
            h2.y = __float2bfloat16(vv[2*p+1]);
            l2.x = __float2bfloat16(vv[2*p]   - __bfloat162float(h2.x));
            l2.y = __float2bfloat16(vv[2*p+1] - __bfloat162float(h2.y));
            hp[p] = *(uint32_t*)&h2;
            lp[p] = *(uint32_t*)&l2;
        }
        uint32_t off = (uint32_t)(r * 256 + ((c ^ (r & 7)) << 4));
        *(uint4*)(smem + AHI + off) = hq;
        *(uint4*)(smem + ALO + off) = lq;
    }
    __syncthreads();

    // stage 1
    float acc[16][4];
    #pragma unroll
    for (int t = 0; t < 16; t++)
        #pragma unroll
        for (int e = 0; e < 4; e++) acc[t][e] = 0.f;
    mma_loop<16>(sb, AHI, ALO, B1HI, B1LO, wid, lane, acc);
    __syncthreads();

    // epilogue 1: bias+ReLU, split to bf16, write back into A buffers
    {
        int rr1 = wid * 16 + (lane >> 2);
        int rr2 = rr1 + 8;
        uint32_t cb1 = (uint32_t)(rr1 * 256);
        uint32_t cb2 = (uint32_t)(rr2 * 256);
        int sw1 = (rr1 & 7), sw2 = (rr2 & 7);
        int cpos = (lane & 3) * 4;
        #pragma unroll
        for (int nt = 0; nt < 16; nt++) {
            int col = nt * 8 + (lane & 3) * 2;
            float2 bb = __ldg((const float2*)(b1 + col));
            float v0 = fmaxf(acc[nt][0] + bb.x, 0.f);
            float v1 = fmaxf(acc[nt][1] + bb.y, 0.f);
            float v2 = fmaxf(acc[nt][2] + bb.x, 0.f);
            float v3 = fmaxf(acc[nt][3] + bb.y, 0.f);
            __nv_bfloat162 h2, l2;
            h2.x = __float2bfloat16(v0);
            h2.y = __float2bfloat16(v1);
            l2.x = __float2bfloat16(v0 - __bfloat162float(h2.x));
            l2.y = __float2bfloat16(v1 - __bfloat162float(h2.y));
            uint32_t o1 = cb1 + ((uint32_t)(nt ^ sw1) << 4) + cpos;
            *(uint32_t*)(smem + AHI + o1) = *(uint32_t*)&h2;
            *(uint32_t*)(smem + ALO + o1) = *(uint32_t*)&l2;
            h2.x = __float2bfloat16(v2);
            h2.y = __float2bfloat16(v3);
            l2.x = __float2bfloat16(v2 - __bfloat162float(h2.x));
            l2.y = __float2bfloat16(v3 - __bfloat162float(h2.y));
            uint32_t o2 = cb2 + ((uint32_t)(nt ^ sw2) << 4) + cpos;
            *(uint32_t*)(smem + AHI + o2) = *(uint32_t*)&h2;
            *(uint32_t*)(smem + ALO + o2) = *(uint32_t*)&l2;
        }
    }
    __syncthreads();

    // stage 2
    float acc2[NT2][4];
    #pragma unroll
    for (int t = 0; t < NT2; t++)
        #pragma unroll
        for (int e = 0; e < 4; e++) acc2[t][e] = 0.f;
    mma_loop<NT2>(sb, AHI, ALO, B2HI, B2LO, wid, lane, acc2);

    int r1 = row0 + wid * 16 + (lane >> 2);
    int r2 = r1 + 8;
    #pragma unroll
    for (int nt = 0; nt < NT2; nt++) {
        int col = nt * 8 + (lane & 3) * 2;
        float2 bb = __ldg((const float2*)(b2 + col));
        float v0 = acc2[nt][0] + bb.x;
        float v1 = acc2[nt][1] + bb.y;
        float v2 = acc2[nt][2] + bb.x;
        float v3 = acc2[nt][3] + bb.y;
        if (r1 < NN) *(float2*)(out + (size_t)r1 * NOUT + col) = make_float2(v0, v1);
        if (r2 < NN) *(float2*)(out + (size_t)r2 * NOUT + col) = make_float2(v2, v3);
    }
}

// ---------------- BN column stats ----------------
template<int NOUT>
__global__ void stats_kernel(const float* __restrict__ h)
{
    constexpr int QC = NOUT / 4;
    constexpr int STEP = 256 / QC;
    __shared__ float ss[NOUT], sq[NOUT];
    int tid = threadIdx.x;
    if (tid < NOUT) { ss[tid] = 0.f; sq[tid] = 0.f; }
    __syncthreads();
    int qc = tid % QC, rg = tid / QC;
    int rend = min(blockIdx.x * 512 + 512, NN);
    float4 s4 = make_float4(0,0,0,0), q4 = make_float4(0,0,0,0);
    for (int r = blockIdx.x * 512 + rg; r < rend; r += STEP) {
        float4 v = __ldg((const float4*)(h + (size_t)r * NOUT) + qc);
        s4.x += v.x; s4.y += v.y; s4.z += v.z; s4.w += v.w;
        q4.x += v.x*v.x; q4.y += v.y*v.y; q4.z += v.z*v.z; q4.w += v.w*v.w;
    }
    int c = qc * 4;
    atomicAdd(&ss[c+0], s4.x); atomicAdd(&ss[c+1], s4.y);
    atomicAdd(&ss[c+2], s4.z); atomicAdd(&ss[c+3], s4.w);
    atomicAdd(&sq[c+0], q4.x); atomicAdd(&sq[c+1], q4.y);
    atomicAdd(&sq[c+2], q4.z); atomicAdd(&sq[c+3], q4.w);
    __syncthreads();
    if (tid < NOUT) {
        atomicAdd(&g_bnstats[tid], ss[tid]);
        atomicAdd(&g_bnstats[NOUT + tid], sq[tid]);
    }
}

// ---------------- BN finalize (resets stats after read) ----------------
__global__ void bn_finalize_kernel(const float* __restrict__ gamma,
                                   const float* __restrict__ beta, int nout)
{
    int c = threadIdx.x;
    if (c < nout) {
        const float invN = 1.0f / (float)NN;
        float sv = g_bnstats[c];
        float qv = g_bnstats[nout + c];
        float mu  = sv * invN;
        float var = qv * invN - mu * mu;
        float s   = gamma[c] * rsqrtf(var + BN_EPS);
        g_scale[c] = s;
        g_shift[c] = beta[c] - mu * s;
        g_bnstats[c] = 0.f;
        g_bnstats[nout + c] = 0.f;
    }
}

// ---------------- pooling (BN+ReLU fused) ----------------
__global__ void pool_sum_kernel(const float* __restrict__ pre, const int* __restrict__ batch)
{
    int t = blockIdx.x * blockDim.x + threadIdx.x;
    if (t >= NN * 16) return;
    int n = t >> 4, q = t & 15;
    int c = q << 2;
    int b = __ldg(batch + n);
    float4 v  = *(const float4*)(pre + (size_t)n * DO_ + c);
    float4 sc = *(const float4*)(g_scale + c);
    float4 sh = *(const float4*)(g_shift + c);
    v.x = fmaxf(fmaf(v.x, sc.x, sh.x), 0.f);
    v.y = fmaxf(fmaf(v.y, sc.y, sh.y), 0.f);
    v.z = fmaxf(fmaf(v.z, sc.z, sh.z), 0.f);
    v.w = fmaxf(fmaf(v.w, sc.w, sh.w), 0.f);
    float* p = g_pool + b * DO_ + c;
    asm volatile("red.global.add.v4.f32 [%0], {%1, %2, %3, %4};"
                 :: "l"(p), "f"(v.x), "f"(v.y), "f"(v.z), "f"(v.w) : "memory");
}

__global__ void pool_cnt_kernel(const int* __restrict__ batch)
{
    __shared__ int sc[NGR];
    for (int i = threadIdx.x; i < NGR; i += blockDim.x) sc[i] = 0;
    __syncthreads();
    for (int i = blockIdx.x * blockDim.x + threadIdx.x; i < NN; i += gridDim.x * blockDim.x)
        atomicAdd(&sc[__ldg(batch + i)], 1);
    __syncthreads();
    for (int i = threadIdx.x; i < NGR; i += blockDim.x)
        if (sc[i]) atomicAdd(&g_cnt[i], sc[i]);
}

__global__ void pool_fin_kernel(float* __restrict__ out)
{
    int i = blockIdx.x * blockDim.x + threadIdx.x;
    if (i < NGR * DO_) {
        int g = i >> 6;
        float c = (float)(g_cnt[g] > 0 ? g_cnt[g] : 1);
        out[i] = g_pool[i] / c;
    }
}

// ---------------- launcher ----------------
extern "C" void kernel_launch(void* const* d_in, const int* in_sizes, int n_in,
                              void* d_out, int out_size)
{
    const float* x     = (const float*)d_in[0];
    const int*   ei    = (const int*)d_in[1];
    const int*   batch = (const int*)d_in[2];
    const float *wA[3], *bA[3], *wB[3], *bB[3], *gam[3], *bet[3];
    for (int l = 0; l < 3; l++) {
        wA[l]  = (const float*)d_in[3 + 6*l + 0];
        bA[l]  = (const float*)d_in[3 + 6*l + 1];
        wB[l]  = (const float*)d_in[3 + 6*l + 2];
        bB[l]  = (const float*)d_in[3 + 6*l + 3];
        gam[l] = (const float*)d_in[3 + 6*l + 4];
        bet[l] = (const float*)d_in[3 + 6*l + 5];
    }
    const int* src = ei;
    const int* dst = ei + NE;

    float *agg, *h1, *h2, *hbn;
    unsigned char *whi, *wlo;
    cudaGetSymbolAddress((void**)&agg,  g_agg);
    cudaGetSymbolAddress((void**)&h1,   g_h1);
    cudaGetSymbolAddress((void**)&h2,   g_h2);
    cudaGetSymbolAddress((void**)&hbn,  g_hbn);
    cudaGetSymbolAddress((void**)&whi,  g_whi);
    cudaGetSymbolAddress((void**)&wlo,  g_wlo);

    constexpr int SMF128 = 65536 + 65536 + 65536;  // 196608
    constexpr int SMF64  = 65536 + 65536 + 32768;  // 163840
    cudaFuncSetAttribute(mlp_mma<128>, cudaFuncAttributeMaxDynamicSharedMemorySize, SMF128);
    cudaFuncSetAttribute(mlp_mma<64>,  cudaFuncAttributeMaxDynamicSharedMemorySize, SMF64);

    const int GB = (NN + 127) / 128;   // 782
    const int EG = (NE + 255) / 256;
    const int GG = (NN + 7) / 8;
    const int SG = (NN + 511) / 512;
    const int AG = (NN * 32 + 255) / 256;   // bn_apply grid

    // ---- CSR build ----
    hist_kernel<<<EG, 256>>>(dst);
    scan_pass1<<<NBLK, 256>>>();
    scan_pass2<<<1, 64>>>();
    scan_pass3<<<NBLK, 256>>>();
    fill_kernel<<<EG, 256>>>(src, dst);

    // ---- W preconvert (+ pool/cnt zeroing) ----
    wconv_kernel<<<(5*16384 + 8192 + 255)/256, 256>>>(wA[0], wB[0], wA[1], wB[1], wA[2], wB[2]);

    // ---- layer 0 ----
    gather_kernel<<<GG, 256>>>(x, agg);
    mlp_mma<128><<<GB, 256, SMF128>>>(agg, whi + 0*32768, wlo + 0*32768, bA[0],
                                      whi + 1*32768, wlo + 1*32768, bB[0], h1);
    stats_kernel<128><<<SG, 256>>>(h1);
    bn_finalize_kernel<<<1, 128>>>(gam[0], bet[0], 128);
    bn_apply_kernel<<<AG, 256>>>(h1, hbn);

    // ---- layer 1 ----
    gather_kernel<<<GG, 256>>>(hbn, agg);
    mlp_mma<128><<<GB, 256, SMF128>>>(agg, whi + 2*32768, wlo + 2*32768, bA[1],
                                      whi + 3*32768, wlo + 3*32768, bB[1], h2);
    stats_kernel<128><<<SG, 256>>>(h2);
    bn_finalize_kernel<<<1, 128>>>(gam[1], bet[1], 128);
    bn_apply_kernel<<<AG, 256>>>(h2, hbn);

    // ---- layer 2 ----
    gather_kernel<<<GG, 256>>>(hbn, agg);
    mlp_mma<64><<<GB, 256, SMF64>>>(agg, whi + 4*32768, wlo + 4*32768, bA[2],
                                    whi + 5*32768, wlo + 5*32768, bB[2], h1);
    stats_kernel<64><<<SG, 256>>>(h1);
    bn_finalize_kernel<<<1, 64>>>(gam[2], bet[2], 64);

    // ---- global mean pool (BN+ReLU fused) ----
    pool_sum_kernel<<<(NN * 16 + 255)/256, 256>>>(h1, batch);
    pool_cnt_kernel<<<296, 256>>>(batch);
    pool_fin_kernel<<<(NGR * DO_ + 255)/256, 256>>>((float*)d_out);
}

// round 13
// speedup vs baseline: 1.6275x; 1.0851x over previous
#include <cuda_runtime.h>
#include <cuda_bf16.h>
#include <cstdint>

#define NN   100000
#define NE   1600000
#define NGR  128
#define D_   128
#define DO_  64
#define BN_EPS 1e-5f
#define SCAN_ELEMS 2048
#define NBLK ((NN + SCAN_ELEMS - 1) / SCAN_ELEMS)   // 49

typedef unsigned long long ull;

// ---------------- scratch ----------------
__device__ __align__(16) float g_agg[(size_t)NN * D_];
__device__ __align__(16) float g_h1 [(size_t)NN * D_];
__device__ __align__(16) float g_h2 [(size_t)NN * D_];
__device__ __align__(16) float g_hbn[(size_t)NN * D_];   // BN+ReLU-applied h
__device__ __align__(16) float g_bnstats[2 * D_];
__device__ __align__(16) float g_scale[D_];
__device__ __align__(16) float g_shift[D_];
__device__ __align__(16) float g_pool[NGR * DO_];
__device__ __align__(16) int   g_cnt[NGR];
// CSR scratch
__device__ __align__(16) int g_deg[NN];
__device__ __align__(16) int g_off[NN + 1];
__device__ __align__(16) int g_cur[NN];
__device__ __align__(16) int g_csr[NE];
__device__ int g_bsum[64];
__device__ int g_bscan[64];
// pre-split A / bf16-rounded W images (hi only now), pre-swizzled
__device__ __align__(16) unsigned char g_whi[6 * 32768];

// ---------------- asm helpers ----------------
__device__ __forceinline__ uint32_t smem_u32(const void* p) {
    uint32_t a;
    asm("{ .reg .u64 t; cvta.to.shared.u64 t, %1; cvt.u32.u64 %0, t; }" : "=r"(a) : "l"(p));
    return a;
}
__device__ __forceinline__ ull add2(ull a, ull b) {
    ull r;
    asm("add.rn.f32x2 %0, %1, %2;" : "=l"(r) : "l"(a), "l"(b));
    return r;
}
__device__ __forceinline__ void ldsm_x4(uint32_t& r0, uint32_t& r1, uint32_t& r2, uint32_t& r3,
                                        uint32_t addr) {
    asm volatile("ldmatrix.sync.aligned.m8n8.x4.shared.b16 {%0,%1,%2,%3}, [%4];"
                 : "=r"(r0), "=r"(r1), "=r"(r2), "=r"(r3) : "r"(addr));
}
__device__ __forceinline__ void ldsm_x4t(uint32_t& r0, uint32_t& r1, uint32_t& r2, uint32_t& r3,
                                         uint32_t addr) {
    asm volatile("ldmatrix.sync.aligned.m8n8.x4.trans.shared.b16 {%0,%1,%2,%3}, [%4];"
                 : "=r"(r0), "=r"(r1), "=r"(r2), "=r"(r3) : "r"(addr));
}
__device__ __forceinline__ void mma16816(float* c, uint32_t a0, uint32_t a1, uint32_t a2,
                                         uint32_t a3, uint32_t b0, uint32_t b1) {
    asm volatile("mma.sync.aligned.m16n8k16.row.col.f32.bf16.bf16.f32 "
                 "{%0,%1,%2,%3}, {%4,%5,%6,%7}, {%8,%9}, {%0,%1,%2,%3};"
                 : "+f"(c[0]), "+f"(c[1]), "+f"(c[2]), "+f"(c[3])
                 : "r"(a0), "r"(a1), "r"(a2), "r"(a3), "r"(b0), "r"(b1));
}

// ---------------- CSR build ----------------
__global__ void hist_kernel(const int* __restrict__ dst) {
    int i = blockIdx.x * blockDim.x + threadIdx.x;
    if (i < NE) atomicAdd(&g_deg[__ldg(dst + i)], 1);
}
__global__ void scan_pass1() {
    __shared__ int ssum[8];
    int b = blockIdx.x, tid = threadIdx.x;
    int base = b * SCAN_ELEMS + tid * 8;
    int s = 0;
    #pragma unroll
    for (int j = 0; j < 8; j++) { int idx = base + j; s += (idx < NN) ? g_deg[idx] : 0; }
    #pragma unroll
    for (int o = 16; o; o >>= 1) s += __shfl_down_sync(0xffffffffu, s, o);
    if ((tid & 31) == 0) ssum[tid >> 5] = s;
    __syncthreads();
    if (tid == 0) {
        int t = 0;
        #pragma unroll
        for (int i = 0; i < 8; i++) t += ssum[i];
        g_bsum[b] = t;
    }
}
__global__ void scan_pass2() {
    int tid = threadIdx.x;
    int v = (tid < NBLK) ? g_bsum[tid] : 0;
    int incl = v, lane = tid & 31;
    #pragma unroll
    for (int o = 1; o < 32; o <<= 1) {
        int y = __shfl_up_sync(0xffffffffu, incl, o);
        if (lane >= o) incl += y;
    }
    __shared__ int w0;
    if (tid == 31) w0 = incl;
    __syncthreads();
    if (tid >= 32) incl += w0;
    if (tid < 64) g_bscan[tid] = incl - v;
    if (tid == 0) g_off[NN] = NE;
}
__global__ void scan_pass3() {
    int b = blockIdx.x, tid = threadIdx.x;
    int base = b * SCAN_ELEMS + tid * 8;
    int vals[8], t = 0;
    #pragma unroll
    for (int j = 0; j < 8; j++) { vals[j] = (base + j < NN) ? g_deg[base + j] : 0; t += vals[j]; }
    int lane = tid & 31, wid = tid >> 5, incl = t;
    #pragma unroll
    for (int o = 1; o < 32; o <<= 1) {
        int y = __shfl_up_sync(0xffffffffu, incl, o);
        if (lane >= o) incl += y;
    }
    __shared__ int wsum[8], woff[8];
    if (lane == 31) wsum[wid] = incl;
    __syncthreads();
    if (tid == 0) { int a = 0; for (int i = 0; i < 8; i++) { woff[i] = a; a += wsum[i]; } }
    __syncthreads();
    int run = g_bscan[b] + woff[wid] + (incl - t);
    #pragma unroll
    for (int j = 0; j < 8; j++) {
        int idx = base + j;
        if (idx < NN) {
            g_off[idx] = run; g_cur[idx] = run; run += vals[j];
            g_deg[idx] = 0;
        }
    }
}
__global__ void fill_kernel(const int* __restrict__ src, const int* __restrict__ dst) {
    int i = blockIdx.x * blockDim.x + threadIdx.x;
    if (i < NE) {
        int d = __ldg(dst + i);
        int p = atomicAdd(&g_cur[d], 1);
        g_csr[p] = __ldg(src + i);
    }
}

// ---------------- W bf16-round + swizzle preconvert (+ pool/cnt zeroing) ----------------
__global__ void wconv_kernel(const float* w0, const float* w1, const float* w2,
                             const float* w3, const float* w4, const float* w5)
{
    int i = blockIdx.x * blockDim.x + threadIdx.x;
    if (i < NGR * DO_) g_pool[i] = 0.f;
    if (i < NGR) g_cnt[i] = 0;
    if (i >= 5 * 16384 + 8192) return;
    int seg = i >> 14;
    int t = i & 16383;
    int nout = (seg == 5) ? 64 : 128;
    const float* W = (seg == 0) ? w0 : (seg == 1) ? w1 : (seg == 2) ? w2
                   : (seg == 3) ? w3 : (seg == 4) ? w4 : w5;
    int k = t / nout, n = t % nout;
    float w = __ldg(W + k * nout + n);
    int pos = k * nout + ((((n >> 3) ^ (k & 7)) << 3) | (n & 7));
    ((__nv_bfloat16*)(g_whi + seg * 32768))[pos] = __float2bfloat16(w);
}

// ---------------- pure-sum gather (f32x2 packed adds) ----------------
__global__ void gather_kernel(const float* __restrict__ h, float* __restrict__ out)
{
    int n = blockIdx.x * 8 + (threadIdx.x >> 5);
    if (n >= NN) return;
    int lane = threadIdx.x & 31;
    const ulonglong2* __restrict__ h2 = (const ulonglong2*)h;

    ulonglong2 s = __ldg(&h2[(size_t)n * 32 + lane]);   // self term
    ull a0 = s.x, b0 = s.y;
    ull a1 = 0, b1 = 0, a2 = 0, b2 = 0, a3 = 0, b3 = 0;

    int j = g_off[n], e1 = g_off[n + 1];
    for (; j + 4 <= e1; j += 4) {
        int i0 = __ldg(&g_csr[j]);
        int i1 = __ldg(&g_csr[j + 1]);
        int i2 = __ldg(&g_csr[j + 2]);
        int i3 = __ldg(&g_csr[j + 3]);
        ulonglong2 w0 = __ldg(&h2[(size_t)i0 * 32 + lane]);
        ulonglong2 w1 = __ldg(&h2[(size_t)i1 * 32 + lane]);
        ulonglong2 w2 = __ldg(&h2[(size_t)i2 * 32 + lane]);
        ulonglong2 w3 = __ldg(&h2[(size_t)i3 * 32 + lane]);
        a0 = add2(a0, w0.x); b0 = add2(b0, w0.y);
        a1 = add2(a1, w1.x); b1 = add2(b1, w1.y);
        a2 = add2(a2, w2.x); b2 = add2(b2, w2.y);
        a3 = add2(a3, w3.x); b3 = add2(b3, w3.y);
    }
    for (; j < e1; j++) {
        int sidx = __ldg(&g_csr[j]);
        ulonglong2 w = __ldg(&h2[(size_t)sidx * 32 + lane]);
        a0 = add2(a0, w.x); b0 = add2(b0, w.y);
    }
    a0 = add2(add2(a0, a1), add2(a2, a3));
    b0 = add2(add2(b0, b1), add2(b2, b3));
    ulonglong2 r; r.x = a0; r.y = b0;
    ((ulonglong2*)out)[(size_t)n * 32 + lane] = r;
}

// ---------------- BN+ReLU apply ----------------
__global__ void bn_apply_kernel(const float* __restrict__ pre, float* __restrict__ outbn)
{
    int i = blockIdx.x * blockDim.x + threadIdx.x;
    if (i >= NN * 32) return;
    int c = (i & 31) << 2;
    float4 v  = __ldg((const float4*)pre + i);
    float4 sc = *(const float4*)(g_scale + c);
    float4 sh = *(const float4*)(g_shift + c);
    v.x = fmaxf(fmaf(v.x, sc.x, sh.x), 0.f);
    v.y = fmaxf(fmaf(v.y, sc.y, sh.y), 0.f);
    v.z = fmaxf(fmaf(v.z, sc.z, sh.z), 0.f);
    v.w = fmaxf(fmaf(v.w, sc.w, sh.w), 0.f);
    ((float4*)outbn)[i] = v;
}

// ---------------- 2-term mma_loop: (Ahi + Alo) @ Bhi ----------------
template<int NT>
__device__ __forceinline__ void mma_loop2(uint32_t sb, uint32_t aHi, uint32_t aLo,
                                          uint32_t bHi, int wid, int lane, float acc[][4])
{
    const int la = lane & 15;
    const int lb = lane >> 4;
    const int l7 = lane & 7;
    const int BR = NT * 16;
    const uint32_t aRow = (uint32_t)((wid * 16 + la) * 256);
    const uint32_t bRow = (uint32_t)(la * BR);
    #pragma unroll 2
    for (int k0 = 0; k0 < 128; k0 += 16) {
        uint32_t kc = (uint32_t)((k0 >> 3) + lb);
        uint32_t aoff = aRow + ((kc ^ (uint32_t)l7) << 4);
        uint32_t ah0, ah1, ah2, ah3, al0, al1, al2, al3;
        ldsm_x4(ah0, ah1, ah2, ah3, sb + aHi + aoff);
        ldsm_x4(al0, al1, al2, al3, sb + aLo + aoff);
        uint32_t bbase = (uint32_t)(k0 * BR) + bRow;
        #pragma unroll
        for (int nt = 0; nt < NT; nt += 2) {
            uint32_t boff = bbase + ((((uint32_t)(nt + lb)) ^ (uint32_t)l7) << 4);
            uint32_t bh0, bh1, bh2, bh3;
            ldsm_x4t(bh0, bh1, bh2, bh3, sb + bHi + boff);
            mma16816(acc[nt],     ah0, ah1, ah2, ah3, bh0, bh1);
            mma16816(acc[nt + 1], ah0, ah1, ah2, ah3, bh2, bh3);
            mma16816(acc[nt],     al0, al1, al2, al3, bh0, bh1);
            mma16816(acc[nt + 1], al0, al1, al2, al3, bh2, bh3);
        }
    }
}

// ---------------- fused 2-GEMM MLP (2-term split: A split, W bf16) ----------------
template<int NOUT>
__global__ __launch_bounds__(256, 1)
void mlp_mma(const float* __restrict__ A,
             const unsigned char* __restrict__ w1h, const float* __restrict__ b1,
             const unsigned char* __restrict__ w2h, const float* __restrict__ b2,
             float* __restrict__ out)
{
    constexpr int NT2  = NOUT / 8;
    constexpr int AHI  = 0;
    constexpr int ALO  = 32768;
    constexpr int B1HI = 65536;
    constexpr int B2HI = 98304;

    extern __shared__ __align__(16) char smem[];
    const uint32_t sb = smem_u32(smem);
    const int tid  = threadIdx.x;
    const int wid  = tid >> 5;
    const int lane = tid & 31;
    const int row0 = blockIdx.x * 128;

    // B tiles (hi only)
    {
        const float4* s1 = (const float4*)w1h;
        float4* d1 = (float4*)(smem + B1HI);
        #pragma unroll
        for (int i = tid; i < 2048; i += 256) d1[i] = s1[i];
        const float4* s3 = (const float4*)w2h;
        float4* d3 = (float4*)(smem + B2HI);
        #pragma unroll
        for (int i = tid; i < NOUT * 16; i += 256) d3[i] = s3[i];
    }
    // A tile: fp32 -> bf16 hi/lo, swizzled
    for (int i = tid; i < 2048; i += 256) {
        int r = i >> 4, c = i & 15;
        int gr = row0 + r;
        float4 v0 = make_float4(0,0,0,0), v1 = make_float4(0,0,0,0);
        if (gr < NN) {
            const float4* ap = (const float4*)(A + (size_t)gr * 128 + c * 8);
            v0 = __ldg(ap); v1 = __ldg(ap + 1);
        }
        float vv[8] = {v0.x, v0.y, v0.z, v0.w, v1.x, v1.y, v1.z, v1.w};
        uint4 hq, lq;
        uint32_t* hp = (uint32_t*)&hq;
        uint32_t* lp = (uint32_t*)&lq;
        #pragma unroll
        for (int p = 0; p < 4; p++) {
            __nv_bfloat162 h2, l2;
            h2.x = __float2bfloat16(vv[2*p]);
            h2.y = __float2bfloat16(vv[2*p+1]);
            l2.x = __float2bfloat16(vv[2*p]   - __bfloat162float(h2.x));
            l2.y = __float2bfloat16(vv[2*p+1] - __bfloat162float(h2.y));
            hp[p] = *(uint32_t*)&h2;
            lp[p] = *(uint32_t*)&l2;
        }
        uint32_t off = (uint32_t)(r * 256 + ((c ^ (r & 7)) << 4));
        *(uint4*)(smem + AHI + off) = hq;
        *(uint4*)(smem + ALO + off) = lq;
    }
    __syncthreads();

    // stage 1
    float acc[16][4];
    #pragma unroll
    for (int t = 0; t < 16; t++)
        #pragma unroll
        for (int e = 0; e < 4; e++) acc[t][e] = 0.f;
    mma_loop2<16>(sb, AHI, ALO, B1HI, wid, lane, acc);
    __syncthreads();

    // epilogue 1: bias+ReLU, split to bf16, write back into A buffers
    {
        int rr1 = wid * 16 + (lane >> 2);
        int rr2 = rr1 + 8;
        uint32_t cb1 = (uint32_t)(rr1 * 256);
        uint32_t cb2 = (uint32_t)(rr2 * 256);
        int sw1 = (rr1 & 7), sw2 = (rr2 & 7);
        int cpos = (lane & 3) * 4;
        #pragma unroll
        for (int nt = 0; nt < 16; nt++) {
            int col = nt * 8 + (lane & 3) * 2;
            float2 bb = __ldg((const float2*)(b1 + col));
            float v0 = fmaxf(acc[nt][0] + bb.x, 0.f);
            float v1 = fmaxf(acc[nt][1] + bb.y, 0.f);
            float v2 = fmaxf(acc[nt][2] + bb.x, 0.f);
            float v3 = fmaxf(acc[nt][3] + bb.y, 0.f);
            __nv_bfloat162 h2, l2;
            h2.x = __float2bfloat16(v0);
            h2.y = __float2bfloat16(v1);
            l2.x = __float2bfloat16(v0 - __bfloat162float(h2.x));
            l2.y = __float2bfloat16(v1 - __bfloat162float(h2.y));
            uint32_t o1 = cb1 + ((uint32_t)(nt ^ sw1) << 4) + cpos;
            *(uint32_t*)(smem + AHI + o1) = *(uint32_t*)&h2;
            *(uint32_t*)(smem + ALO + o1) = *(uint32_t*)&l2;
            h2.x = __float2bfloat16(v2);
            h2.y = __float2bfloat16(v3);
            l2.x = __float2bfloat16(v2 - __bfloat162float(h2.x));
            l2.y = __float2bfloat16(v3 - __bfloat162float(h2.y));
            uint32_t o2 = cb2 + ((uint32_t)(nt ^ sw2) << 4) + cpos;
            *(uint32_t*)(smem + AHI + o2) = *(uint32_t*)&h2;
            *(uint32_t*)(smem + ALO + o2) = *(uint32_t*)&l2;
        }
    }
    __syncthreads();

    // stage 2
    float acc2[NT2][4];
    #pragma unroll
    for (int t = 0; t < NT2; t++)
        #pragma unroll
        for (int e = 0; e < 4; e++) acc2[t][e] = 0.f;
    mma_loop2<NT2>(sb, AHI, ALO, B2HI, wid, lane, acc2);

    int r1 = row0 + wid * 16 + (lane >> 2);
    int r2 = r1 + 8;
    #pragma unroll
    for (int nt = 0; nt < NT2; nt++) {
        int col = nt * 8 + (lane & 3) * 2;
        float2 bb = __ldg((const float2*)(b2 + col));
        float v0 = acc2[nt][0] + bb.x;
        float v1 = acc2[nt][1] + bb.y;
        float v2 = acc2[nt][2] + bb.x;
        float v3 = acc2[nt][3] + bb.y;
        if (r1 < NN) *(float2*)(out + (size_t)r1 * NOUT + col) = make_float2(v0, v1);
        if (r2 < NN) *(float2*)(out + (size_t)r2 * NOUT + col) = make_float2(v2, v3);
    }
}

// ---------------- BN column stats ----------------
template<int NOUT>
__global__ void stats_kernel(const float* __restrict__ h)
{
    constexpr int QC = NOUT / 4;
    constexpr int STEP = 256 / QC;
    __shared__ float ss[NOUT], sq[NOUT];
    int tid = threadIdx.x;
    if (tid < NOUT) { ss[tid] = 0.f; sq[tid] = 0.f; }
    __syncthreads();
    int qc = tid % QC, rg = tid / QC;
    int rend = min(blockIdx.x * 512 + 512, NN);
    float4 s4 = make_float4(0,0,0,0), q4 = make_float4(0,0,0,0);
    for (int r = blockIdx.x * 512 + rg; r < rend; r += STEP) {
        float4 v = __ldg((const float4*)(h + (size_t)r * NOUT) + qc);
        s4.x += v.x; s4.y += v.y; s4.z += v.z; s4.w += v.w;
        q4.x += v.x*v.x; q4.y += v.y*v.y; q4.z += v.z*v.z; q4.w += v.w*v.w;
    }
    int c = qc * 4;
    atomicAdd(&ss[c+0], s4.x); atomicAdd(&ss[c+1], s4.y);
    atomicAdd(&ss[c+2], s4.z); atomicAdd(&ss[c+3], s4.w);
    atomicAdd(&sq[c+0], q4.x); atomicAdd(&sq[c+1], q4.y);
    atomicAdd(&sq[c+2], q4.z); atomicAdd(&sq[c+3], q4.w);
    __syncthreads();
    if (tid < NOUT) {
        atomicAdd(&g_bnstats[tid], ss[tid]);
        atomicAdd(&g_bnstats[NOUT + tid], sq[tid]);
    }
}

// ---------------- BN finalize (resets stats after read) ----------------
__global__ void bn_finalize_kernel(const float* __restrict__ gamma,
                                   const float* __restrict__ beta, int nout)
{
    int c = threadIdx.x;
    if (c < nout) {
        const float invN = 1.0f / (float)NN;
        float sv = g_bnstats[c];
        float qv = g_bnstats[nout + c];
        float mu  = sv * invN;
        float var = qv * invN - mu * mu;
        float s   = gamma[c] * rsqrtf(var + BN_EPS);
        g_scale[c] = s;
        g_shift[c] = beta[c] - mu * s;
        g_bnstats[c] = 0.f;
        g_bnstats[nout + c] = 0.f;
    }
}

// ---------------- pooling (BN+ReLU fused) ----------------
__global__ void pool_sum_kernel(const float* __restrict__ pre, const int* __restrict__ batch)
{
    int t = blockIdx.x * blockDim.x + threadIdx.x;
    if (t >= NN * 16) return;
    int n = t >> 4, q = t & 15;
    int c = q << 2;
    int b = __ldg(batch + n);
    float4 v  = *(const float4*)(pre + (size_t)n * DO_ + c);
    float4 sc = *(const float4*)(g_scale + c);
    float4 sh = *(const float4*)(g_shift + c);
    v.x = fmaxf(fmaf(v.x, sc.x, sh.x), 0.f);
    v.y = fmaxf(fmaf(v.y, sc.y, sh.y), 0.f);
    v.z = fmaxf(fmaf(v.z, sc.z, sh.z), 0.f);
    v.w = fmaxf(fmaf(v.w, sc.w, sh.w), 0.f);
    float* p = g_pool + b * DO_ + c;
    asm volatile("red.global.add.v4.f32 [%0], {%1, %2, %3, %4};"
                 :: "l"(p), "f"(v.x), "f"(v.y), "f"(v.z), "f"(v.w) : "memory");
}

__global__ void pool_cnt_kernel(const int* __restrict__ batch)
{
    __shared__ int sc[NGR];
    for (int i = threadIdx.x; i < NGR; i += blockDim.x) sc[i] = 0;
    __syncthreads();
    for (int i = blockIdx.x * blockDim.x + threadIdx.x; i < NN; i += gridDim.x * blockDim.x)
        atomicAdd(&sc[__ldg(batch + i)], 1);
    __syncthreads();
    for (int i = threadIdx.x; i < NGR; i += blockDim.x)
        if (sc[i]) atomicAdd(&g_cnt[i], sc[i]);
}

__global__ void pool_fin_kernel(float* __restrict__ out)
{
    int i = blockIdx.x * blockDim.x + threadIdx.x;
    if (i < NGR * DO_) {
        int g = i >> 6;
        float c = (float)(g_cnt[g] > 0 ? g_cnt[g] : 1);
        out[i] = g_pool[i] / c;
    }
}

// ---------------- launcher ----------------
extern "C" void kernel_launch(void* const* d_in, const int* in_sizes, int n_in,
                              void* d_out, int out_size)
{
    const float* x     = (const float*)d_in[0];
    const int*   ei    = (const int*)d_in[1];
    const int*   batch = (const int*)d_in[2];
    const float *wA[3], *bA[3], *wB[3], *bB[3], *gam[3], *bet[3];
    for (int l = 0; l < 3; l++) {
        wA[l]  = (const float*)d_in[3 + 6*l + 0];
        bA[l]  = (const float*)d_in[3 + 6*l + 1];
        wB[l]  = (const float*)d_in[3 + 6*l + 2];
        bB[l]  = (const float*)d_in[3 + 6*l + 3];
        gam[l] = (const float*)d_in[3 + 6*l + 4];
        bet[l] = (const float*)d_in[3 + 6*l + 5];
    }
    const int* src = ei;
    const int* dst = ei + NE;

    float *agg, *h1, *h2, *hbn;
    unsigned char *whi;
    cudaGetSymbolAddress((void**)&agg,  g_agg);
    cudaGetSymbolAddress((void**)&h1,   g_h1);
    cudaGetSymbolAddress((void**)&h2,   g_h2);
    cudaGetSymbolAddress((void**)&hbn,  g_hbn);
    cudaGetSymbolAddress((void**)&whi,  g_whi);

    constexpr int SMF128 = 65536 + 32768 + 32768;  // 131072
    constexpr int SMF64  = 65536 + 32768 + 16384;  // 114688
    cudaFuncSetAttribute(mlp_mma<128>, cudaFuncAttributeMaxDynamicSharedMemorySize, SMF128);
    cudaFuncSetAttribute(mlp_mma<64>,  cudaFuncAttributeMaxDynamicSharedMemorySize, SMF64);

    const int GB = (NN + 127) / 128;   // 782
    const int EG = (NE + 255) / 256;
    const int GG = (NN + 7) / 8;
    const int SG = (NN + 511) / 512;
    const int AG = (NN * 32 + 255) / 256;

    // ---- CSR build (launches 1-5), then gather is launch #6 (ncu -s 5 target) ----
    hist_kernel<<<EG, 256>>>(dst);
    scan_pass1<<<NBLK, 256>>>();
    scan_pass2<<<1, 64>>>();
    scan_pass3<<<NBLK, 256>>>();
    fill_kernel<<<EG, 256>>>(src, dst);

    // ---- layer 0 gather (launch #6) ----
    gather_kernel<<<GG, 256>>>(x, agg);

    // ---- W preconvert (+ pool/cnt zeroing) — needed before first MLP ----
    wconv_kernel<<<(5*16384 + 8192 + 255)/256, 256>>>(wA[0], wB[0], wA[1], wB[1], wA[2], wB[2]);

    // ---- layer 0 MLP ----
    mlp_mma<128><<<GB, 256, SMF128>>>(agg, whi + 0*32768, bA[0], whi + 1*32768, bB[0], h1);
    stats_kernel<128><<<SG, 256>>>(h1);
    bn_finalize_kernel<<<1, 128>>>(gam[0], bet[0], 128);
    bn_apply_kernel<<<AG, 256>>>(h1, hbn);

    // ---- layer 1 ----
    gather_kernel<<<GG, 256>>>(hbn, agg);
    mlp_mma<128><<<GB, 256, SMF128>>>(agg, whi + 2*32768, bA[1], whi + 3*32768, bB[1], h2);
    stats_kernel<128><<<SG, 256>>>(h2);
    bn_finalize_kernel<<<1, 128>>>(gam[1], bet[1], 128);
    bn_apply_kernel<<<AG, 256>>>(h2, hbn);

    // ---- layer 2 ----
    gather_kernel<<<GG, 256>>>(hbn, agg);
    mlp_mma<64><<<GB, 256, SMF64>>>(agg, whi + 4*32768, bA[2], whi + 5*32768, bB[2], h1);
    stats_kernel<64><<<SG, 256>>>(h1);
    bn_finalize_kernel<<<1, 64>>>(gam[2], bet[2], 64);

    // ---- global mean pool (BN+ReLU fused) ----
    pool_sum_kernel<<<(NN * 16 + 255)/256, 256>>>(h1, batch);
    pool_cnt_kernel<<<296, 256>>>(batch);
    pool_fin_kernel<<<(NGR * DO_ + 255)/256, 256>>>((float*)d_out);
}

// round 14
// speedup vs baseline: 1.7373x; 1.0675x over previous
#include <cuda_runtime.h>
#include <cuda_bf16.h>
#include <cstdint>

#define NN   100000
#define NE   1600000
#define NGR  128
#define D_   128
#define DO_  64
#define BN_EPS 1e-5f
#define SCAN_ELEMS 2048
#define NBLK ((NN + SCAN_ELEMS - 1) / SCAN_ELEMS)   // 49

typedef unsigned long long ull;

// ---------------- scratch ----------------
__device__ __align__(16) float g_agg[(size_t)NN * D_];
__device__ __align__(16) float g_h1 [(size_t)NN * D_];
__device__ __align__(16) float g_h2 [(size_t)NN * D_];
__device__ __align__(16) __nv_bfloat16 g_hbnb[(size_t)NN * D_];  // BN+ReLU-applied h, bf16
__device__ __align__(16) float g_bnstats[2 * D_];
__device__ __align__(16) float g_scale[D_];
__device__ __align__(16) float g_shift[D_];
__device__ __align__(16) float g_pool[NGR * DO_];
__device__ __align__(16) int   g_cnt[NGR];
// CSR scratch
__device__ __align__(16) int g_deg[NN];
__device__ __align__(16) int g_off[NN + 1];
__device__ __align__(16) int g_cur[NN];
__device__ __align__(16) int g_csr[NE];
__device__ int g_bsum[64];
__device__ int g_bscan[64];
// bf16-rounded, pre-swizzled W images
__device__ __align__(16) unsigned char g_whi[6 * 32768];

// ---------------- asm helpers ----------------
__device__ __forceinline__ uint32_t smem_u32(const void* p) {
    uint32_t a;
    asm("{ .reg .u64 t; cvta.to.shared.u64 t, %1; cvt.u32.u64 %0, t; }" : "=r"(a) : "l"(p));
    return a;
}
__device__ __forceinline__ ull add2(ull a, ull b) {
    ull r;
    asm("add.rn.f32x2 %0, %1, %2;" : "=l"(r) : "l"(a), "l"(b));
    return r;
}
// expand packed bf16x2 -> packed f32x2 (pure bit ops: f32 bits = bf16 bits << 16)
__device__ __forceinline__ ull bexp(uint32_t v) {
    return ((ull)(v & 0xffff0000u) << 32) | (ull)(v << 16);
}
__device__ __forceinline__ void ldsm_x4(uint32_t& r0, uint32_t& r1, uint32_t& r2, uint32_t& r3,
                                        uint32_t addr) {
    asm volatile("ldmatrix.sync.aligned.m8n8.x4.shared.b16 {%0,%1,%2,%3}, [%4];"
                 : "=r"(r0), "=r"(r1), "=r"(r2), "=r"(r3) : "r"(addr));
}
__device__ __forceinline__ void ldsm_x4t(uint32_t& r0, uint32_t& r1, uint32_t& r2, uint32_t& r3,
                                         uint32_t addr) {
    asm volatile("ldmatrix.sync.aligned.m8n8.x4.trans.shared.b16 {%0,%1,%2,%3}, [%4];"
                 : "=r"(r0), "=r"(r1), "=r"(r2), "=r"(r3) : "r"(addr));
}
__device__ __forceinline__ void mma16816(float* c, uint32_t a0, uint32_t a1, uint32_t a2,
                                         uint32_t a3, uint32_t b0, uint32_t b1) {
    asm volatile("mma.sync.aligned.m16n8k16.row.col.f32.bf16.bf16.f32 "
                 "{%0,%1,%2,%3}, {%4,%5,%6,%7}, {%8,%9}, {%0,%1,%2,%3};"
                 : "+f"(c[0]), "+f"(c[1]), "+f"(c[2]), "+f"(c[3])
                 : "r"(a0), "r"(a1), "r"(a2), "r"(a3), "r"(b0), "r"(b1));
}

// ---------------- CSR build ----------------
__global__ void hist_kernel(const int* __restrict__ dst) {
    int i = blockIdx.x * blockDim.x + threadIdx.x;
    if (i < NE) atomicAdd(&g_deg[__ldg(dst + i)], 1);
}
__global__ void scan_pass1() {
    __shared__ int ssum[8];
    int b = blockIdx.x, tid = threadIdx.x;
    int base = b * SCAN_ELEMS + tid * 8;
    int s = 0;
    #pragma unroll
    for (int j = 0; j < 8; j++) { int idx = base + j; s += (idx < NN) ? g_deg[idx] : 0; }
    #pragma unroll
    for (int o = 16; o; o >>= 1) s += __shfl_down_sync(0xffffffffu, s, o);
    if ((tid & 31) == 0) ssum[tid >> 5] = s;
    __syncthreads();
    if (tid == 0) {
        int t = 0;
        #pragma unroll
        for (int i = 0; i < 8; i++) t += ssum[i];
        g_bsum[b] = t;
    }
}
__global__ void scan_pass2() {
    int tid = threadIdx.x;
    int v = (tid < NBLK) ? g_bsum[tid] : 0;
    int incl = v, lane = tid & 31;
    #pragma unroll
    for (int o = 1; o < 32; o <<= 1) {
        int y = __shfl_up_sync(0xffffffffu, incl, o);
        if (lane >= o) incl += y;
    }
    __shared__ int w0;
    if (tid == 31) w0 = incl;
    __syncthreads();
    if (tid >= 32) incl += w0;
    if (tid < 64) g_bscan[tid] = incl - v;
    if (tid == 0) g_off[NN] = NE;
}
__global__ void scan_pass3() {
    int b = blockIdx.x, tid = threadIdx.x;
    int base = b * SCAN_ELEMS + tid * 8;
    int vals[8], t = 0;
    #pragma unroll
    for (int j = 0; j < 8; j++) { vals[j] = (base + j < NN) ? g_deg[base + j] : 0; t += vals[j]; }
    int lane = tid & 31, wid = tid >> 5, incl = t;
    #pragma unroll
    for (int o = 1; o < 32; o <<= 1) {
        int y = __shfl_up_sync(0xffffffffu, incl, o);
        if (lane >= o) incl += y;
    }
    __shared__ int wsum[8], woff[8];
    if (lane == 31) wsum[wid] = incl;
    __syncthreads();
    if (tid == 0) { int a = 0; for (int i = 0; i < 8; i++) { woff[i] = a; a += wsum[i]; } }
    __syncthreads();
    int run = g_bscan[b] + woff[wid] + (incl - t);
    #pragma unroll
    for (int j = 0; j < 8; j++) {
        int idx = base + j;
        if (idx < NN) {
            g_off[idx] = run; g_cur[idx] = run; run += vals[j];
            g_deg[idx] = 0;
        }
    }
}
__global__ void fill_kernel(const int* __restrict__ src, const int* __restrict__ dst) {
    int i = blockIdx.x * blockDim.x + threadIdx.x;
    if (i < NE) {
        int d = __ldg(dst + i);
        int p = atomicAdd(&g_cur[d], 1);
        g_csr[p] = __ldg(src + i);
    }
}

// ---------------- W bf16-round + swizzle preconvert (+ pool/cnt zeroing) ----------------
__global__ void wconv_kernel(const float* w0, const float* w1, const float* w2,
                             const float* w3, const float* w4, const float* w5)
{
    int i = blockIdx.x * blockDim.x + threadIdx.x;
    if (i < NGR * DO_) g_pool[i] = 0.f;
    if (i < NGR) g_cnt[i] = 0;
    if (i >= 5 * 16384 + 8192) return;
    int seg = i >> 14;
    int t = i & 16383;
    int nout = (seg == 5) ? 64 : 128;
    const float* W = (seg == 0) ? w0 : (seg == 1) ? w1 : (seg == 2) ? w2
                   : (seg == 3) ? w3 : (seg == 4) ? w4 : w5;
    int k = t / nout, n = t % nout;
    float w = __ldg(W + k * nout + n);
    int pos = k * nout + ((((n >> 3) ^ (k & 7)) << 3) | (n & 7));
    ((__nv_bfloat16*)(g_whi + seg * 32768))[pos] = __float2bfloat16(w);
}

// ---------------- pure-sum gather, fp32 source (layer 0) ----------------
__global__ void gather_kernel(const float* __restrict__ h, float* __restrict__ out)
{
    int n = blockIdx.x * 8 + (threadIdx.x >> 5);
    if (n >= NN) return;
    int lane = threadIdx.x & 31;
    const ulonglong2* __restrict__ h2 = (const ulonglong2*)h;

    ulonglong2 s = __ldg(&h2[(size_t)n * 32 + lane]);
    ull a0 = s.x, b0 = s.y;
    ull a1 = 0, b1 = 0, a2 = 0, b2 = 0, a3 = 0, b3 = 0;

    int j = g_off[n], e1 = g_off[n + 1];
    for (; j + 4 <= e1; j += 4) {
        int i0 = __ldg(&g_csr[j]);
        int i1 = __ldg(&g_csr[j + 1]);
        int i2 = __ldg(&g_csr[j + 2]);
        int i3 = __ldg(&g_csr[j + 3]);
        ulonglong2 w0 = __ldg(&h2[(size_t)i0 * 32 + lane]);
        ulonglong2 w1 = __ldg(&h2[(size_t)i1 * 32 + lane]);
        ulonglong2 w2 = __ldg(&h2[(size_t)i2 * 32 + lane]);
        ulonglong2 w3 = __ldg(&h2[(size_t)i3 * 32 + lane]);
        a0 = add2(a0, w0.x); b0 = add2(b0, w0.y);
        a1 = add2(a1, w1.x); b1 = add2(b1, w1.y);
        a2 = add2(a2, w2.x); b2 = add2(b2, w2.y);
        a3 = add2(a3, w3.x); b3 = add2(b3, w3.y);
    }
    for (; j < e1; j++) {
        int sidx = __ldg(&g_csr[j]);
        ulonglong2 w = __ldg(&h2[(size_t)sidx * 32 + lane]);
        a0 = add2(a0, w.x); b0 = add2(b0, w.y);
    }
    a0 = add2(add2(a0, a1), add2(a2, a3));
    b0 = add2(add2(b0, b1), add2(b2, b3));
    ulonglong2 r; r.x = a0; r.y = b0;
    ((ulonglong2*)out)[(size_t)n * 32 + lane] = r;
}

// ---------------- pure-sum gather, bf16 source (layers 1,2) — half the traffic --------
__global__ void gather_bf16_kernel(float* __restrict__ out)
{
    int n = blockIdx.x * 8 + (threadIdx.x >> 5);
    if (n >= NN) return;
    int lane = threadIdx.x & 31;
    const uint2* __restrict__ hb = (const uint2*)g_hbnb;   // 8 B = 4 bf16 per lane

    uint2 s = __ldg(&hb[(size_t)n * 32 + lane]);
    ull a0 = bexp(s.x), b0 = bexp(s.y);
    ull a1 = 0, b1 = 0, a2 = 0, b2 = 0, a3 = 0, b3 = 0;

    int j = g_off[n], e1 = g_off[n + 1];
    for (; j + 4 <= e1; j += 4) {
        int i0 = __ldg(&g_csr[j]);
        int i1 = __ldg(&g_csr[j + 1]);
        int i2 = __ldg(&g_csr[j + 2]);
        int i3 = __ldg(&g_csr[j + 3]);
        uint2 w0 = __ldg(&hb[(size_t)i0 * 32 + lane]);
        uint2 w1 = __ldg(&hb[(size_t)i1 * 32 + lane]);
        uint2 w2 = __ldg(&hb[(size_t)i2 * 32 + lane]);
        uint2 w3 = __ldg(&hb[(size_t)i3 * 32 + lane]);
        a0 = add2(a0, bexp(w0.x)); b0 = add2(b0, bexp(w0.y));
        a1 = add2(a1, bexp(w1.x)); b1 = add2(b1, bexp(w1.y));
        a2 = add2(a2, bexp(w2.x)); b2 = add2(b2, bexp(w2.y));
        a3 = add2(a3, bexp(w3.x)); b3 = add2(b3, bexp(w3.y));
    }
    for (; j < e1; j++) {
        int sidx = __ldg(&g_csr[j]);
        uint2 w = __ldg(&hb[(size_t)sidx * 32 + lane]);
        a0 = add2(a0, bexp(w.x)); b0 = add2(b0, bexp(w.y));
    }
    a0 = add2(add2(a0, a1), add2(a2, a3));
    b0 = add2(add2(b0, b1), add2(b2, b3));
    ulonglong2 r; r.x = a0; r.y = b0;
    ((ulonglong2*)out)[(size_t)n * 32 + lane] = r;
}

// ---------------- BN+ReLU apply -> bf16 ----------------
__global__ void bn_apply_kernel(const float* __restrict__ pre)
{
    int i = blockIdx.x * blockDim.x + threadIdx.x;
    if (i >= NN * 32) return;            // float4 units (d=128)
    int c = (i & 31) << 2;
    float4 v  = __ldg((const float4*)pre + i);
    float4 sc = *(const float4*)(g_scale + c);
    float4 sh = *(const float4*)(g_shift + c);
    v.x = fmaxf(fmaf(v.x, sc.x, sh.x), 0.f);
    v.y = fmaxf(fmaf(v.y, sc.y, sh.y), 0.f);
    v.z = fmaxf(fmaf(v.z, sc.z, sh.z), 0.f);
    v.w = fmaxf(fmaf(v.w, sc.w, sh.w), 0.f);
    __nv_bfloat162 p0, p1;
    p0.x = __float2bfloat16(v.x); p0.y = __float2bfloat16(v.y);
    p1.x = __float2bfloat16(v.z); p1.y = __float2bfloat16(v.w);
    uint2 o;
    o.x = *(uint32_t*)&p0; o.y = *(uint32_t*)&p1;
    ((uint2*)g_hbnb)[i] = o;
}

// ---------------- 2-term mma_loop: (Ahi + Alo) @ Bhi ----------------
template<int NT>
__device__ __forceinline__ void mma_loop2(uint32_t sb, uint32_t aHi, uint32_t aLo,
                                          uint32_t bHi, int wid, int lane, float acc[][4])
{
    const int la = lane & 15;
    const int lb = lane >> 4;
    const int l7 = lane & 7;
    const int BR = NT * 16;
    const uint32_t aRow = (uint32_t)((wid * 16 + la) * 256);
    const uint32_t bRow = (uint32_t)(la * BR);
    #pragma unroll 2
    for (int k0 = 0; k0 < 128; k0 += 16) {
        uint32_t kc = (uint32_t)((k0 >> 3) + lb);
        uint32_t aoff = aRow + ((kc ^ (uint32_t)l7) << 4);
        uint32_t ah0, ah1, ah2, ah3, al0, al1, al2, al3;
        ldsm_x4(ah0, ah1, ah2, ah3, sb + aHi + aoff);
        ldsm_x4(al0, al1, al2, al3, sb + aLo + aoff);
        uint32_t bbase = (uint32_t)(k0 * BR) + bRow;
        #pragma unroll
        for (int nt = 0; nt < NT; nt += 2) {
            uint32_t boff = bbase + ((((uint32_t)(nt + lb)) ^ (uint32_t)l7) << 4);
            uint32_t bh0, bh1, bh2, bh3;
            ldsm_x4t(bh0, bh1, bh2, bh3, sb + bHi + boff);
            mma16816(acc[nt],     ah0, ah1, ah2, ah3, bh0, bh1);
            mma16816(acc[nt + 1], ah0, ah1, ah2, ah3, bh2, bh3);
            mma16816(acc[nt],     al0, al1, al2, al3, bh0, bh1);
            mma16816(acc[nt + 1], al0, al1, al2, al3, bh2, bh3);
        }
    }
}

// ---------------- fused 2-GEMM MLP (2-term split: A split, W bf16) ----------------
template<int NOUT>
__global__ __launch_bounds__(256, 1)
void mlp_mma(const float* __restrict__ A,
             const unsigned char* __restrict__ w1h, const float* __restrict__ b1,
             const unsigned char* __restrict__ w2h, const float* __restrict__ b2,
             float* __restrict__ out)
{
    constexpr int NT2  = NOUT / 8;
    constexpr int AHI  = 0;
    constexpr int ALO  = 32768;
    constexpr int B1HI = 65536;
    constexpr int B2HI = 98304;

    extern __shared__ __align__(16) char smem[];
    const uint32_t sb = smem_u32(smem);
    const int tid  = threadIdx.x;
    const int wid  = tid >> 5;
    const int lane = tid & 31;
    const int row0 = blockIdx.x * 128;

    // B tiles (hi only)
    {
        const float4* s1 = (const float4*)w1h;
        float4* d1 = (float4*)(smem + B1HI);
        #pragma unroll
        for (int i = tid; i < 2048; i += 256) d1[i] = s1[i];
        const float4* s3 = (const float4*)w2h;
        float4* d3 = (float4*)(smem + B2HI);
        #pragma unroll
        for (int i = tid; i < NOUT * 16; i += 256) d3[i] = s3[i];
    }
    // A tile: fp32 -> bf16 hi/lo, swizzled
    for (int i = tid; i < 2048; i += 256) {
        int r = i >> 4, c = i & 15;
        int gr = row0 + r;
        float4 v0 = make_float4(0,0,0,0), v1 = make_float4(0,0,0,0);
        if (gr < NN) {
            const float4* ap = (const float4*)(A + (size_t)gr * 128 + c * 8);
            v0 = __ldg(ap); v1 = __ldg(ap + 1);
        }
        float vv[8] = {v0.x, v0.y, v0.z, v0.w, v1.x, v1.y, v1.z, v1.w};
        uint4 hq, lq;
        uint32_t* hp = (uint32_t*)&hq;
        uint32_t* lp = (uint32_t*)&lq;
        #pragma unroll
        for (int p = 0; p < 4; p++) {
            __nv_bfloat162 h2, l2;
            h2.x = __float2bfloat16(vv[2*p]);
            h2.y = __float2bfloat16(vv[2*p+1]);
            l2.x = __float2bfloat16(vv[2*p]   - __bfloat162float(h2.x));
            l2.y = __float2bfloat16(vv[2*p+1] - __bfloat162float(h2.y));
            hp[p] = *(uint32_t*)&h2;
            lp[p] = *(uint32_t*)&l2;
        }
        uint32_t off = (uint32_t)(r * 256 + ((c ^ (r & 7)) << 4));
        *(uint4*)(smem + AHI + off) = hq;
        *(uint4*)(smem + ALO + off) = lq;
    }
    __syncthreads();

    // stage 1
    float acc[16][4];
    #pragma unroll
    for (int t = 0; t < 16; t++)
        #pragma unroll
        for (int e = 0; e < 4; e++) acc[t][e] = 0.f;
    mma_loop2<16>(sb, AHI, ALO, B1HI, wid, lane, acc);
    __syncthreads();

    // epilogue 1: bias+ReLU, split to bf16, write back into A buffers
    {
        int rr1 = wid * 16 + (lane >> 2);
        int rr2 = rr1 + 8;
        uint32_t cb1 = (uint32_t)(rr1 * 256);
        uint32_t cb2 = (uint32_t)(rr2 * 256);
        int sw1 = (rr1 & 7), sw2 = (rr2 & 7);
        int cpos = (lane & 3) * 4;
        #pragma unroll
        for (int nt = 0; nt < 16; nt++) {
            int col = nt * 8 + (lane & 3) * 2;
            float2 bb = __ldg((const float2*)(b1 + col));
            float v0 = fmaxf(acc[nt][0] + bb.x, 0.f);
            float v1 = fmaxf(acc[nt][1] + bb.y, 0.f);
            float v2 = fmaxf(acc[nt][2] + bb.x, 0.f);
            float v3 = fmaxf(acc[nt][3] + bb.y, 0.f);
            __nv_bfloat162 h2, l2;
            h2.x = __float2bfloat16(v0);
            h2.y = __float2bfloat16(v1);
            l2.x = __float2bfloat16(v0 - __bfloat162float(h2.x));
            l2.y = __float2bfloat16(v1 - __bfloat162float(h2.y));
            uint32_t o1 = cb1 + ((uint32_t)(nt ^ sw1) << 4) + cpos;
            *(uint32_t*)(smem + AHI + o1) = *(uint32_t*)&h2;
            *(uint32_t*)(smem + ALO + o1) = *(uint32_t*)&l2;
            h2.x = __float2bfloat16(v2);
            h2.y = __float2bfloat16(v3);
            l2.x = __float2bfloat16(v2 - __bfloat162float(h2.x));
            l2.y = __float2bfloat16(v3 - __bfloat162float(h2.y));
            uint32_t o2 = cb2 + ((uint32_t)(nt ^ sw2) << 4) + cpos;
            *(uint32_t*)(smem + AHI + o2) = *(uint32_t*)&h2;
            *(uint32_t*)(smem + ALO + o2) = *(uint32_t*)&l2;
        }
    }
    __syncthreads();

    // stage 2
    float acc2[NT2][4];
    #pragma unroll
    for (int t = 0; t < NT2; t++)
        #pragma unroll
        for (int e = 0; e < 4; e++) acc2[t][e] = 0.f;
    mma_loop2<NT2>(sb, AHI, ALO, B2HI, wid, lane, acc2);

    int r1 = row0 + wid * 16 + (lane >> 2);
    int r2 = r1 + 8;
    #pragma unroll
    for (int nt = 0; nt < NT2; nt++) {
        int col = nt * 8 + (lane & 3) * 2;
        float2 bb = __ldg((const float2*)(b2 + col));
        float v0 = acc2[nt][0] + bb.x;
        float v1 = acc2[nt][1] + bb.y;
        float v2 = acc2[nt][2] + bb.x;
        float v3 = acc2[nt][3] + bb.y;
        if (r1 < NN) *(float2*)(out + (size_t)r1 * NOUT + col) = make_float2(v0, v1);
        if (r2 < NN) *(float2*)(out + (size_t)r2 * NOUT + col) = make_float2(v2, v3);
    }
}

// ---------------- BN column stats ----------------
template<int NOUT>
__global__ void stats_kernel(const float* __restrict__ h)
{
    constexpr int QC = NOUT / 4;
    constexpr int STEP = 256 / QC;
    __shared__ float ss[NOUT], sq[NOUT];
    int tid = threadIdx.x;
    if (tid < NOUT) { ss[tid] = 0.f; sq[tid] = 0.f; }
    __syncthreads();
    int qc = tid % QC, rg = tid / QC;
    int rend = min(blockIdx.x * 512 + 512, NN);
    float4 s4 = make_float4(0,0,0,0), q4 = make_float4(0,0,0,0);
    for (int r = blockIdx.x * 512 + rg; r < rend; r += STEP) {
        float4 v = __ldg((const float4*)(h + (size_t)r * NOUT) + qc);
        s4.x += v.x; s4.y += v.y; s4.z += v.z; s4.w += v.w;
        q4.x += v.x*v.x; q4.y += v.y*v.y; q4.z += v.z*v.z; q4.w += v.w*v.w;
    }
    int c = qc * 4;
    atomicAdd(&ss[c+0], s4.x); atomicAdd(&ss[c+1], s4.y);
    atomicAdd(&ss[c+2], s4.z); atomicAdd(&ss[c+3], s4.w);
    atomicAdd(&sq[c+0], q4.x); atomicAdd(&sq[c+1], q4.y);
    atomicAdd(&sq[c+2], q4.z); atomicAdd(&sq[c+3], q4.w);
    __syncthreads();
    if (tid < NOUT) {
        atomicAdd(&g_bnstats[tid], ss[tid]);
        atomicAdd(&g_bnstats[NOUT + tid], sq[tid]);
    }
}

// ---------------- BN finalize (resets stats after read) ----------------
__global__ void bn_finalize_kernel(const float* __restrict__ gamma,
                                   const float* __restrict__ beta, int nout)
{
    int c = threadIdx.x;
    if (c < nout) {
        const float invN = 1.0f / (float)NN;
        float sv = g_bnstats[c];
        float qv = g_bnstats[nout + c];
        float mu  = sv * invN;
        float var = qv * invN - mu * mu;
        float s   = gamma[c] * rsqrtf(var + BN_EPS);
        g_scale[c] = s;
        g_shift[c] = beta[c] - mu * s;
        g_bnstats[c] = 0.f;
        g_bnstats[nout + c] = 0.f;
    }
}

// ---------------- pooling (BN+ReLU fused) ----------------
__global__ void pool_sum_kernel(const float* __restrict__ pre, const int* __restrict__ batch)
{
    int t = blockIdx.x * blockDim.x + threadIdx.x;
    if (t >= NN * 16) return;
    int n = t >> 4, q = t & 15;
    int c = q << 2;
    int b = __ldg(batch + n);
    float4 v  = *(const float4*)(pre + (size_t)n * DO_ + c);
    float4 sc = *(const float4*)(g_scale + c);
    float4 sh = *(const float4*)(g_shift + c);
    v.x = fmaxf(fmaf(v.x, sc.x, sh.x), 0.f);
    v.y = fmaxf(fmaf(v.y, sc.y, sh.y), 0.f);
    v.z = fmaxf(fmaf(v.z, sc.z, sh.z), 0.f);
    v.w = fmaxf(fmaf(v.w, sc.w, sh.w), 0.f);
    float* p = g_pool + b * DO_ + c;
    asm volatile("red.global.add.v4.f32 [%0], {%1, %2, %3, %4};"
                 :: "l"(p), "f"(v.x), "f"(v.y), "f"(v.z), "f"(v.w) : "memory");
}

__global__ void pool_cnt_kernel(const int* __restrict__ batch)
{
    __shared__ int sc[NGR];
    for (int i = threadIdx.x; i < NGR; i += blockDim.x) sc[i] = 0;
    __syncthreads();
    for (int i = blockIdx.x * blockDim.x + threadIdx.x; i < NN; i += gridDim.x * blockDim.x)
        atomicAdd(&sc[__ldg(batch + i)], 1);
    __syncthreads();
    for (int i = threadIdx.x; i < NGR; i += blockDim.x)
        if (sc[i]) atomicAdd(&g_cnt[i], sc[i]);
}

__global__ void pool_fin_kernel(float* __restrict__ out)
{
    int i = blockIdx.x * blockDim.x + threadIdx.x;
    if (i < NGR * DO_) {
        int g = i >> 6;
        float c = (float)(g_cnt[g] > 0 ? g_cnt[g] : 1);
        out[i] = g_pool[i] / c;
    }
}

// ---------------- launcher ----------------
extern "C" void kernel_launch(void* const* d_in, const int* in_sizes, int n_in,
                              void* d_out, int out_size)
{
    const float* x     = (const float*)d_in[0];
    const int*   ei    = (const int*)d_in[1];
    const int*   batch = (const int*)d_in[2];
    const float *wA[3], *bA[3], *wB[3], *bB[3], *gam[3], *bet[3];
    for (int l = 0; l < 3; l++) {
        wA[l]  = (const float*)d_in[3 + 6*l + 0];
        bA[l]  = (const float*)d_in[3 + 6*l + 1];
        wB[l]  = (const float*)d_in[3 + 6*l + 2];
        bB[l]  = (const float*)d_in[3 + 6*l + 3];
        gam[l] = (const float*)d_in[3 + 6*l + 4];
        bet[l] = (const float*)d_in[3 + 6*l + 5];
    }
    const int* src = ei;
    const int* dst = ei + NE;

    float *agg, *h1, *h2;
    unsigned char *whi;
    cudaGetSymbolAddress((void**)&agg,  g_agg);
    cudaGetSymbolAddress((void**)&h1,   g_h1);
    cudaGetSymbolAddress((void**)&h2,   g_h2);
    cudaGetSymbolAddress((void**)&whi,  g_whi);

    constexpr int SMF128 = 65536 + 32768 + 32768;  // 131072
    constexpr int SMF64  = 65536 + 32768 + 16384;  // 114688
    cudaFuncSetAttribute(mlp_mma<128>, cudaFuncAttributeMaxDynamicSharedMemorySize, SMF128);
    cudaFuncSetAttribute(mlp_mma<64>,  cudaFuncAttributeMaxDynamicSharedMemorySize, SMF64);

    const int GB = (NN + 127) / 128;   // 782
    const int EG = (NE + 255) / 256;
    const int GG = (NN + 7) / 8;
    const int SG = (NN + 511) / 512;
    const int AG = (NN * 32 + 255) / 256;

    // ---- CSR build ----
    hist_kernel<<<EG, 256>>>(dst);
    scan_pass1<<<NBLK, 256>>>();
    scan_pass2<<<1, 64>>>();
    scan_pass3<<<NBLK, 256>>>();
    fill_kernel<<<EG, 256>>>(src, dst);

    // ---- layer 0 gather (launch #6, ncu target) ----
    gather_kernel<<<GG, 256>>>(x, agg);

    // ---- W preconvert (+ pool/cnt zeroing) ----
    wconv_kernel<<<(5*16384 + 8192 + 255)/256, 256>>>(wA[0], wB[0], wA[1], wB[1], wA[2], wB[2]);

    // ---- layer 0 MLP ----
    mlp_mma<128><<<GB, 256, SMF128>>>(agg, whi + 0*32768, bA[0], whi + 1*32768, bB[0], h1);
    stats_kernel<128><<<SG, 256>>>(h1);
    bn_finalize_kernel<<<1, 128>>>(gam[0], bet[0], 128);
    bn_apply_kernel<<<AG, 256>>>(h1);

    // ---- layer 1 (bf16 gather) ----
    gather_bf16_kernel<<<GG, 256>>>(agg);
    mlp_mma<128><<<GB, 256, SMF128>>>(agg, whi + 2*32768, bA[1], whi + 3*32768, bB[1], h2);
    stats_kernel<128><<<SG, 256>>>(h2);
    bn_finalize_kernel<<<1, 128>>>(gam[1], bet[1], 128);
    bn_apply_kernel<<<AG, 256>>>(h2);

    // ---- layer 2 (bf16 gather) ----
    gather_bf16_kernel<<<GG, 256>>>(agg);
    mlp_mma<64><<<GB, 256, SMF64>>>(agg, whi + 4*32768, bA[2], whi + 5*32768, bB[2], h1);
    stats_kernel<64><<<SG, 256>>>(h1);
    bn_finalize_kernel<<<1, 64>>>(gam[2], bet[2], 64);

    // ---- global mean pool (BN+ReLU fused) ----
    pool_sum_kernel<<<(NN * 16 + 255)/256, 256>>>(h1, batch);
    pool_cnt_kernel<<<296, 256>>>(batch);
    pool_fin_kernel<<<(NGR * DO_ + 255)/256, 256>>>((float*)d_out);
}

// round 15
// speedup vs baseline: 1.8922x; 1.0891x over previous
#include <cuda_runtime.h>
#include <cuda_bf16.h>
#include <cstdint>

#define NN   100000
#define NE   1600000
#define NGR  128
#define D_   128
#define DO_  64
#define BN_EPS 1e-5f
#define SCAN_ELEMS 2048
#define NBLK ((NN + SCAN_ELEMS - 1) / SCAN_ELEMS)   // 49

typedef unsigned long long ull;

// ---------------- scratch ----------------
__device__ __align__(16) float g_agg[(size_t)NN * D_];                 // gather output (fp32 sums)
__device__ __align__(16) __nv_bfloat16 g_xb [(size_t)NN * D_];         // bf16 x
__device__ __align__(16) __nv_bfloat16 g_h1 [(size_t)NN * D_];         // bf16 pre-BN h
__device__ __align__(16) __nv_bfloat16 g_h2 [(size_t)NN * D_];
__device__ __align__(16) __nv_bfloat16 g_hbnb[(size_t)NN * D_];        // bf16 post-BN h
__device__ __align__(16) float g_bnstats[2 * D_];
__device__ __align__(16) float g_scale[D_];
__device__ __align__(16) float g_shift[D_];
__device__ __align__(16) float g_pool[NGR * DO_];
__device__ __align__(16) int   g_cnt[NGR];
// CSR scratch
__device__ __align__(16) int g_deg[NN];
__device__ __align__(16) int g_off[NN + 1];
__device__ __align__(16) int g_cur[NN];
__device__ __align__(16) int g_csr[NE];
__device__ int g_bsum[64];
__device__ int g_bscan[64];
// bf16-rounded, pre-swizzled W images
__device__ __align__(16) unsigned char g_whi[6 * 32768];

// ---------------- asm helpers ----------------
__device__ __forceinline__ uint32_t smem_u32(const void* p) {
    uint32_t a;
    asm("{ .reg .u64 t; cvta.to.shared.u64 t, %1; cvt.u32.u64 %0, t; }" : "=r"(a) : "l"(p));
    return a;
}
__device__ __forceinline__ ull add2(ull a, ull b) {
    ull r;
    asm("add.rn.f32x2 %0, %1, %2;" : "=l"(r) : "l"(a), "l"(b));
    return r;
}
// expand packed bf16x2 -> packed f32x2 (pure bit ops)
__device__ __forceinline__ ull bexp(uint32_t v) {
    return ((ull)(v & 0xffff0000u) << 32) | (ull)(v << 16);
}
__device__ __forceinline__ float4 bexp4(uint2 r) {
    float4 o;
    o.x = __uint_as_float(r.x << 16);
    o.y = __uint_as_float(r.x & 0xffff0000u);
    o.z = __uint_as_float(r.y << 16);
    o.w = __uint_as_float(r.y & 0xffff0000u);
    return o;
}
__device__ __forceinline__ void ldsm_x4(uint32_t& r0, uint32_t& r1, uint32_t& r2, uint32_t& r3,
                                        uint32_t addr) {
    asm volatile("ldmatrix.sync.aligned.m8n8.x4.shared.b16 {%0,%1,%2,%3}, [%4];"
                 : "=r"(r0), "=r"(r1), "=r"(r2), "=r"(r3) : "r"(addr));
}
__device__ __forceinline__ void ldsm_x4t(uint32_t& r0, uint32_t& r1, uint32_t& r2, uint32_t& r3,
                                         uint32_t addr) {
    asm volatile("ldmatrix.sync.aligned.m8n8.x4.trans.shared.b16 {%0,%1,%2,%3}, [%4];"
                 : "=r"(r0), "=r"(r1), "=r"(r2), "=r"(r3) : "r"(addr));
}
__device__ __forceinline__ void mma16816(float* c, uint32_t a0, uint32_t a1, uint32_t a2,
                                         uint32_t a3, uint32_t b0, uint32_t b1) {
    asm volatile("mma.sync.aligned.m16n8k16.row.col.f32.bf16.bf16.f32 "
                 "{%0,%1,%2,%3}, {%4,%5,%6,%7}, {%8,%9}, {%0,%1,%2,%3};"
                 : "+f"(c[0]), "+f"(c[1]), "+f"(c[2]), "+f"(c[3])
                 : "r"(a0), "r"(a1), "r"(a2), "r"(a3), "r"(b0), "r"(b1));
}

// ---------------- CSR build ----------------
__global__ void hist_kernel(const int* __restrict__ dst) {
    int i = blockIdx.x * blockDim.x + threadIdx.x;
    if (i < NE) atomicAdd(&g_deg[__ldg(dst + i)], 1);
}
__global__ void scan_pass1() {
    __shared__ int ssum[8];
    int b = blockIdx.x, tid = threadIdx.x;
    int base = b * SCAN_ELEMS + tid * 8;
    int s = 0;
    #pragma unroll
    for (int j = 0; j < 8; j++) { int idx = base + j; s += (idx < NN) ? g_deg[idx] : 0; }
    #pragma unroll
    for (int o = 16; o; o >>= 1) s += __shfl_down_sync(0xffffffffu, s, o);
    if ((tid & 31) == 0) ssum[tid >> 5] = s;
    __syncthreads();
    if (tid == 0) {
        int t = 0;
        #pragma unroll
        for (int i = 0; i < 8; i++) t += ssum[i];
        g_bsum[b] = t;
    }
}
__global__ void scan_pass2() {
    int tid = threadIdx.x;
    int v = (tid < NBLK) ? g_bsum[tid] : 0;
    int incl = v, lane = tid & 31;
    #pragma unroll
    for (int o = 1; o < 32; o <<= 1) {
        int y = __shfl_up_sync(0xffffffffu, incl, o);
        if (lane >= o) incl += y;
    }
    __shared__ int w0;
    if (tid == 31) w0 = incl;
    __syncthreads();
    if (tid >= 32) incl += w0;
    if (tid < 64) g_bscan[tid] = incl - v;
    if (tid == 0) g_off[NN] = NE;
}
__global__ void scan_pass3() {
    int b = blockIdx.x, tid = threadIdx.x;
    int base = b * SCAN_ELEMS + tid * 8;
    int vals[8], t = 0;
    #pragma unroll
    for (int j = 0; j < 8; j++) { vals[j] = (base + j < NN) ? g_deg[base + j] : 0; t += vals[j]; }
    int lane = tid & 31, wid = tid >> 5, incl = t;
    #pragma unroll
    for (int o = 1; o < 32; o <<= 1) {
        int y = __shfl_up_sync(0xffffffffu, incl, o);
        if (lane >= o) incl += y;
    }
    __shared__ int wsum[8], woff[8];
    if (lane == 31) wsum[wid] = incl;
    __syncthreads();
    if (tid == 0) { int a = 0; for (int i = 0; i < 8; i++) { woff[i] = a; a += wsum[i]; } }
    __syncthreads();
    int run = g_bscan[b] + woff[wid] + (incl - t);
    #pragma unroll
    for (int j = 0; j < 8; j++) {
        int idx = base + j;
        if (idx < NN) {
            g_off[idx] = run; g_cur[idx] = run; run += vals[j];
            g_deg[idx] = 0;
        }
    }
}
__global__ void fill_kernel(const int* __restrict__ src, const int* __restrict__ dst) {
    int i = blockIdx.x * blockDim.x + threadIdx.x;
    if (i < NE) {
        int d = __ldg(dst + i);
        int p = atomicAdd(&g_cur[d], 1);
        g_csr[p] = __ldg(src + i);
    }
}

// ---------------- x -> bf16 preconvert ----------------
__global__ void xconv_kernel(const float* __restrict__ x)
{
    int i = blockIdx.x * blockDim.x + threadIdx.x;
    if (i >= NN * 32) return;
    float4 v = __ldg((const float4*)x + i);
    __nv_bfloat162 p0, p1;
    p0.x = __float2bfloat16(v.x); p0.y = __float2bfloat16(v.y);
    p1.x = __float2bfloat16(v.z); p1.y = __float2bfloat16(v.w);
    uint2 o;
    o.x = *(uint32_t*)&p0; o.y = *(uint32_t*)&p1;
    ((uint2*)g_xb)[i] = o;
}

// ---------------- W bf16-round + swizzle preconvert (+ pool/cnt zeroing) ----------------
__global__ void wconv_kernel(const float* w0, const float* w1, const float* w2,
                             const float* w3, const float* w4, const float* w5)
{
    int i = blockIdx.x * blockDim.x + threadIdx.x;
    if (i < NGR * DO_) g_pool[i] = 0.f;
    if (i < NGR) g_cnt[i] = 0;
    if (i >= 5 * 16384 + 8192) return;
    int seg = i >> 14;
    int t = i & 16383;
    int nout = (seg == 5) ? 64 : 128;
    const float* W = (seg == 0) ? w0 : (seg == 1) ? w1 : (seg == 2) ? w2
                   : (seg == 3) ? w3 : (seg == 4) ? w4 : w5;
    int k = t / nout, n = t % nout;
    float w = __ldg(W + k * nout + n);
    int pos = k * nout + ((((n >> 3) ^ (k & 7)) << 3) | (n & 7));
    ((__nv_bfloat16*)(g_whi + seg * 32768))[pos] = __float2bfloat16(w);
}

// ---------------- pure-sum gather, bf16 source (all layers) ----------------
__global__ void gather_bf16_kernel(const __nv_bfloat16* __restrict__ hsrc,
                                   float* __restrict__ out)
{
    int n = blockIdx.x * 8 + (threadIdx.x >> 5);
    if (n >= NN) return;
    int lane = threadIdx.x & 31;
    const uint2* __restrict__ hb = (const uint2*)hsrc;

    uint2 s = __ldg(&hb[(size_t)n * 32 + lane]);
    ull a0 = bexp(s.x), b0 = bexp(s.y);
    ull a1 = 0, b1 = 0, a2 = 0, b2 = 0, a3 = 0, b3 = 0;

    int j = g_off[n], e1 = g_off[n + 1];
    for (; j + 4 <= e1; j += 4) {
        int i0 = __ldg(&g_csr[j]);
        int i1 = __ldg(&g_csr[j + 1]);
        int i2 = __ldg(&g_csr[j + 2]);
        int i3 = __ldg(&g_csr[j + 3]);
        uint2 w0 = __ldg(&hb[(size_t)i0 * 32 + lane]);
        uint2 w1 = __ldg(&hb[(size_t)i1 * 32 + lane]);
        uint2 w2 = __ldg(&hb[(size_t)i2 * 32 + lane]);
        uint2 w3 = __ldg(&hb[(size_t)i3 * 32 + lane]);
        a0 = add2(a0, bexp(w0.x)); b0 = add2(b0, bexp(w0.y));
        a1 = add2(a1, bexp(w1.x)); b1 = add2(b1, bexp(w1.y));
        a2 = add2(a2, bexp(w2.x)); b2 = add2(b2, bexp(w2.y));
        a3 = add2(a3, bexp(w3.x)); b3 = add2(b3, bexp(w3.y));
    }
    for (; j < e1; j++) {
        int sidx = __ldg(&g_csr[j]);
        uint2 w = __ldg(&hb[(size_t)sidx * 32 + lane]);
        a0 = add2(a0, bexp(w.x)); b0 = add2(b0, bexp(w.y));
    }
    a0 = add2(add2(a0, a1), add2(a2, a3));
    b0 = add2(add2(b0, b1), add2(b2, b3));
    ulonglong2 r; r.x = a0; r.y = b0;
    ((ulonglong2*)out)[(size_t)n * 32 + lane] = r;
}

// ---------------- BN+ReLU apply: bf16 h -> bf16 hbn ----------------
__global__ void bn_apply_kernel(const __nv_bfloat16* __restrict__ pre)
{
    int i = blockIdx.x * blockDim.x + threadIdx.x;
    if (i >= NN * 32) return;            // uint2 units (4 bf16 each, d=128)
    int c = (i & 31) << 2;
    float4 v  = bexp4(__ldg((const uint2*)pre + i));
    float4 sc = *(const float4*)(g_scale + c);
    float4 sh = *(const float4*)(g_shift + c);
    v.x = fmaxf(fmaf(v.x, sc.x, sh.x), 0.f);
    v.y = fmaxf(fmaf(v.y, sc.y, sh.y), 0.f);
    v.z = fmaxf(fmaf(v.z, sc.z, sh.z), 0.f);
    v.w = fmaxf(fmaf(v.w, sc.w, sh.w), 0.f);
    __nv_bfloat162 p0, p1;
    p0.x = __float2bfloat16(v.x); p0.y = __float2bfloat16(v.y);
    p1.x = __float2bfloat16(v.z); p1.y = __float2bfloat16(v.w);
    uint2 o;
    o.x = *(uint32_t*)&p0; o.y = *(uint32_t*)&p1;
    ((uint2*)g_hbnb)[i] = o;
}

// ---------------- 2-term mma_loop: (Ahi + Alo) @ Bhi ----------------
template<int NT>
__device__ __forceinline__ void mma_loop2(uint32_t sb, uint32_t aHi, uint32_t aLo,
                                          uint32_t bHi, int wid, int lane, float acc[][4])
{
    const int la = lane & 15;
    const int lb = lane >> 4;
    const int l7 = lane & 7;
    const int BR = NT * 16;
    const uint32_t aRow = (uint32_t)((wid * 16 + la) * 256);
    const uint32_t bRow = (uint32_t)(la * BR);
    #pragma unroll 2
    for (int k0 = 0; k0 < 128; k0 += 16) {
        uint32_t kc = (uint32_t)((k0 >> 3) + lb);
        uint32_t aoff = aRow + ((kc ^ (uint32_t)l7) << 4);
        uint32_t ah0, ah1, ah2, ah3, al0, al1, al2, al3;
        ldsm_x4(ah0, ah1, ah2, ah3, sb + aHi + aoff);
        ldsm_x4(al0, al1, al2, al3, sb + aLo + aoff);
        uint32_t bbase = (uint32_t)(k0 * BR) + bRow;
        #pragma unroll
        for (int nt = 0; nt < NT; nt += 2) {
            uint32_t boff = bbase + ((((uint32_t)(nt + lb)) ^ (uint32_t)l7) << 4);
            uint32_t bh0, bh1, bh2, bh3;
            ldsm_x4t(bh0, bh1, bh2, bh3, sb + bHi + boff);
            mma16816(acc[nt],     ah0, ah1, ah2, ah3, bh0, bh1);
            mma16816(acc[nt + 1], ah0, ah1, ah2, ah3, bh2, bh3);
            mma16816(acc[nt],     al0, al1, al2, al3, bh0, bh1);
            mma16816(acc[nt + 1], al0, al1, al2, al3, bh2, bh3);
        }
    }
}

// ---------------- fused 2-GEMM MLP (A split-bf16, W bf16, bf16 output) -------------
template<int NOUT>
__global__ __launch_bounds__(256, 1)
void mlp_mma(const float* __restrict__ A,
             const unsigned char* __restrict__ w1h, const float* __restrict__ b1,
             const unsigned char* __restrict__ w2h, const float* __restrict__ b2,
             __nv_bfloat16* __restrict__ out)
{
    constexpr int NT2  = NOUT / 8;
    constexpr int AHI  = 0;
    constexpr int ALO  = 32768;
    constexpr int B1HI = 65536;
    constexpr int B2HI = 98304;

    extern __shared__ __align__(16) char smem[];
    const uint32_t sb = smem_u32(smem);
    const int tid  = threadIdx.x;
    const int wid  = tid >> 5;
    const int lane = tid & 31;
    const int row0 = blockIdx.x * 128;

    // B tiles (hi only)
    {
        const float4* s1 = (const float4*)w1h;
        float4* d1 = (float4*)(smem + B1HI);
        #pragma unroll
        for (int i = tid; i < 2048; i += 256) d1[i] = s1[i];
        const float4* s3 = (const float4*)w2h;
        float4* d3 = (float4*)(smem + B2HI);
        #pragma unroll
        for (int i = tid; i < NOUT * 16; i += 256) d3[i] = s3[i];
    }
    // A tile: fp32 -> bf16 hi/lo, swizzled
    for (int i = tid; i < 2048; i += 256) {
        int r = i >> 4, c = i & 15;
        int gr = row0 + r;
        float4 v0 = make_float4(0,0,0,0), v1 = make_float4(0,0,0,0);
        if (gr < NN) {
            const float4* ap = (const float4*)(A + (size_t)gr * 128 + c * 8);
            v0 = __ldg(ap); v1 = __ldg(ap + 1);
        }
        float vv[8] = {v0.x, v0.y, v0.z, v0.w, v1.x, v1.y, v1.z, v1.w};
        uint4 hq, lq;
        uint32_t* hp = (uint32_t*)&hq;
        uint32_t* lp = (uint32_t*)&lq;
        #pragma unroll
        for (int p = 0; p < 4; p++) {
            __nv_bfloat162 h2, l2;
            h2.x = __float2bfloat16(vv[2*p]);
            h2.y = __float2bfloat16(vv[2*p+1]);
            l2.x = __float2bfloat16(vv[2*p]   - __bfloat162float(h2.x));
            l2.y = __float2bfloat16(vv[2*p+1] - __bfloat162float(h2.y));
            hp[p] = *(uint32_t*)&h2;
            lp[p] = *(uint32_t*)&l2;
        }
        uint32_t off = (uint32_t)(r * 256 + ((c ^ (r & 7)) << 4));
        *(uint4*)(smem + AHI + off) = hq;
        *(uint4*)(smem + ALO + off) = lq;
    }
    __syncthreads();

    // stage 1
    float acc[16][4];
    #pragma unroll
    for (int t = 0; t < 16; t++)
        #pragma unroll
        for (int e = 0; e < 4; e++) acc[t][e] = 0.f;
    mma_loop2<16>(sb, AHI, ALO, B1HI, wid, lane, acc);
    __syncthreads();

    // epilogue 1: bias+ReLU, split to bf16, write back into A buffers
    {
        int rr1 = wid * 16 + (lane >> 2);
        int rr2 = rr1 + 8;
        uint32_t cb1 = (uint32_t)(rr1 * 256);
        uint32_t cb2 = (uint32_t)(rr2 * 256);
        int sw1 = (rr1 & 7), sw2 = (rr2 & 7);
        int cpos = (lane & 3) * 4;
        #pragma unroll
        for (int nt = 0; nt < 16; nt++) {
            int col = nt * 8 + (lane & 3) * 2;
            float2 bb = __ldg((const float2*)(b1 + col));
            float v0 = fmaxf(acc[nt][0] + bb.x, 0.f);
            float v1 = fmaxf(acc[nt][1] + bb.y, 0.f);
            float v2 = fmaxf(acc[nt][2] + bb.x, 0.f);
            float v3 = fmaxf(acc[nt][3] + bb.y, 0.f);
            __nv_bfloat162 h2, l2;
            h2.x = __float2bfloat16(v0);
            h2.y = __float2bfloat16(v1);
            l2.x = __float2bfloat16(v0 - __bfloat162float(h2.x));
            l2.y = __float2bfloat16(v1 - __bfloat162float(h2.y));
            uint32_t o1 = cb1 + ((uint32_t)(nt ^ sw1) << 4) + cpos;
            *(uint32_t*)(smem + AHI + o1) = *(uint32_t*)&h2;
            *(uint32_t*)(smem + ALO + o1) = *(uint32_t*)&l2;
            h2.x = __float2bfloat16(v2);
            h2.y = __float2bfloat16(v3);
            l2.x = __float2bfloat16(v2 - __bfloat162float(h2.x));
            l2.y = __float2bfloat16(v3 - __bfloat162float(h2.y));
            uint32_t o2 = cb2 + ((uint32_t)(nt ^ sw2) << 4) + cpos;
            *(uint32_t*)(smem + AHI + o2) = *(uint32_t*)&h2;
            *(uint32_t*)(smem + ALO + o2) = *(uint32_t*)&l2;
        }
    }
    __syncthreads();

    // stage 2
    float acc2[NT2][4];
    #pragma unroll
    for (int t = 0; t < NT2; t++)
        #pragma unroll
        for (int e = 0; e < 4; e++) acc2[t][e] = 0.f;
    mma_loop2<NT2>(sb, AHI, ALO, B2HI, wid, lane, acc2);

    int r1 = row0 + wid * 16 + (lane >> 2);
    int r2 = r1 + 8;
    #pragma unroll
    for (int nt = 0; nt < NT2; nt++) {
        int col = nt * 8 + (lane & 3) * 2;
        float2 bb = __ldg((const float2*)(b2 + col));
        float v0 = acc2[nt][0] + bb.x;
        float v1 = acc2[nt][1] + bb.y;
        float v2 = acc2[nt][2] + bb.x;
        float v3 = acc2[nt][3] + bb.y;
        if (r1 < NN) {
            __nv_bfloat162 p;
            p.x = __float2bfloat16(v0); p.y = __float2bfloat16(v1);
            *(uint32_t*)(out + (size_t)r1 * NOUT + col) = *(uint32_t*)&p;
        }
        if (r2 < NN) {
            __nv_bfloat162 p;
            p.x = __float2bfloat16(v2); p.y = __float2bfloat16(v3);
            *(uint32_t*)(out + (size_t)r2 * NOUT + col) = *(uint32_t*)&p;
        }
    }
}

// ---------------- BN column stats (bf16 input, fp32 accumulation) ----------------
template<int NOUT>
__global__ void stats_kernel(const __nv_bfloat16* __restrict__ h)
{
    constexpr int QC = NOUT / 4;
    constexpr int STEP = 256 / QC;
    __shared__ float ss[NOUT], sq[NOUT];
    int tid = threadIdx.x;
    if (tid < NOUT) { ss[tid] = 0.f; sq[tid] = 0.f; }
    __syncthreads();
    int qc = tid % QC, rg = tid / QC;
    int rend = min(blockIdx.x * 512 + 512, NN);
    float4 s4 = make_float4(0,0,0,0), q4 = make_float4(0,0,0,0);
    for (int r = blockIdx.x * 512 + rg; r < rend; r += STEP) {
        float4 v = bexp4(__ldg((const uint2*)h + (size_t)r * QC + qc));
        s4.x += v.x; s4.y += v.y; s4.z += v.z; s4.w += v.w;
        q4.x += v.x*v.x; q4.y += v.y*v.y; q4.z += v.z*v.z; q4.w += v.w*v.w;
    }
    int c = qc * 4;
    atomicAdd(&ss[c+0], s4.x); atomicAdd(&ss[c+1], s4.y);
    atomicAdd(&ss[c+2], s4.z); atomicAdd(&ss[c+3], s4.w);
    atomicAdd(&sq[c+0], q4.x); atomicAdd(&sq[c+1], q4.y);
    atomicAdd(&sq[c+2], q4.z); atomicAdd(&sq[c+3], q4.w);
    __syncthreads();
    if (tid < NOUT) {
        atomicAdd(&g_bnstats[tid], ss[tid]);
        atomicAdd(&g_bnstats[NOUT + tid], sq[tid]);
    }
}

// ---------------- BN finalize (resets stats after read) ----------------
__global__ void bn_finalize_kernel(const float* __restrict__ gamma,
                                   const float* __restrict__ beta, int nout)
{
    int c = threadIdx.x;
    if (c < nout) {
        const float invN = 1.0f / (float)NN;
        float sv = g_bnstats[c];
        float qv = g_bnstats[nout + c];
        float mu  = sv * invN;
        float var = qv * invN - mu * mu;
        float s   = gamma[c] * rsqrtf(var + BN_EPS);
        g_scale[c] = s;
        g_shift[c] = beta[c] - mu * s;
        g_bnstats[c] = 0.f;
        g_bnstats[nout + c] = 0.f;
    }
}

// ---------------- pooling (BN+ReLU fused, bf16 input) ----------------
__global__ void pool_sum_kernel(const __nv_bfloat16* __restrict__ pre,
                                const int* __restrict__ batch)
{
    int t = blockIdx.x * blockDim.x + threadIdx.x;
    if (t >= NN * 16) return;
    int n = t >> 4, q = t & 15;
    int c = q << 2;
    int b = __ldg(batch + n);
    float4 v  = bexp4(__ldg((const uint2*)pre + (size_t)n * 16 + q));
    float4 sc = *(const float4*)(g_scale + c);
    float4 sh = *(const float4*)(g_shift + c);
    v.x = fmaxf(fmaf(v.x, sc.x, sh.x), 0.f);
    v.y = fmaxf(fmaf(v.y, sc.y, sh.y), 0.f);
    v.z = fmaxf(fmaf(v.z, sc.z, sh.z), 0.f);
    v.w = fmaxf(fmaf(v.w, sc.w, sh.w), 0.f);
    float* p = g_pool + b * DO_ + c;
    asm volatile("red.global.add.v4.f32 [%0], {%1, %2, %3, %4};"
                 :: "l"(p), "f"(v.x), "f"(v.y), "f"(v.z), "f"(v.w) : "memory");
}

__global__ void pool_cnt_kernel(const int* __restrict__ batch)
{
    __shared__ int sc[NGR];
    for (int i = threadIdx.x; i < NGR; i += blockDim.x) sc[i] = 0;
    __syncthreads();
    for (int i = blockIdx.x * blockDim.x + threadIdx.x; i < NN; i += gridDim.x * blockDim.x)
        atomicAdd(&sc[__ldg(batch + i)], 1);
    __syncthreads();
    for (int i = threadIdx.x; i < NGR; i += blockDim.x)
        if (sc[i]) atomicAdd(&g_cnt[i], sc[i]);
}

__global__ void pool_fin_kernel(float* __restrict__ out)
{
    int i = blockIdx.x * blockDim.x + threadIdx.x;
    if (i < NGR * DO_) {
        int g = i >> 6;
        float c = (float)(g_cnt[g] > 0 ? g_cnt[g] : 1);
        out[i] = g_pool[i] / c;
    }
}

// ---------------- launcher ----------------
extern "C" void kernel_launch(void* const* d_in, const int* in_sizes, int n_in,
                              void* d_out, int out_size)
{
    const float* x     = (const float*)d_in[0];
    const int*   ei    = (const int*)d_in[1];
    const int*   batch = (const int*)d_in[2];
    const float *wA[3], *bA[3], *wB[3], *bB[3], *gam[3], *bet[3];
    for (int l = 0; l < 3; l++) {
        wA[l]  = (const float*)d_in[3 + 6*l + 0];
        bA[l]  = (const float*)d_in[3 + 6*l + 1];
        wB[l]  = (const float*)d_in[3 + 6*l + 2];
        bB[l]  = (const float*)d_in[3 + 6*l + 3];
        gam[l] = (const float*)d_in[3 + 6*l + 4];
        bet[l] = (const float*)d_in[3 + 6*l + 5];
    }
    const int* src = ei;
    const int* dst = ei + NE;

    float *agg;
    __nv_bfloat16 *xb, *h1, *h2, *hbnb;
    unsigned char *whi;
    cudaGetSymbolAddress((void**)&agg,  g_agg);
    cudaGetSymbolAddress((void**)&xb,   g_xb);
    cudaGetSymbolAddress((void**)&h1,   g_h1);
    cudaGetSymbolAddress((void**)&h2,   g_h2);
    cudaGetSymbolAddress((void**)&hbnb, g_hbnb);
    cudaGetSymbolAddress((void**)&whi,  g_whi);

    constexpr int SMF128 = 65536 + 32768 + 32768;  // 131072
    constexpr int SMF64  = 65536 + 32768 + 16384;  // 114688
    cudaFuncSetAttribute(mlp_mma<128>, cudaFuncAttributeMaxDynamicSharedMemorySize, SMF128);
    cudaFuncSetAttribute(mlp_mma<64>,  cudaFuncAttributeMaxDynamicSharedMemorySize, SMF64);

    const int GB = (NN + 127) / 128;   // 782
    const int EG = (NE + 255) / 256;
    const int GG = (NN + 7) / 8;
    const int SG = (NN + 511) / 512;
    const int AG = (NN * 32 + 255) / 256;

    // ---- CSR build ----
    hist_kernel<<<EG, 256>>>(dst);
    scan_pass1<<<NBLK, 256>>>();
    scan_pass2<<<1, 64>>>();
    scan_pass3<<<NBLK, 256>>>();
    fill_kernel<<<EG, 256>>>(src, dst);

    // ---- x -> bf16 + W preconvert (+ pool/cnt zeroing) ----
    xconv_kernel<<<AG, 256>>>(x);
    wconv_kernel<<<(5*16384 + 8192 + 255)/256, 256>>>(wA[0], wB[0], wA[1], wB[1], wA[2], wB[2]);

    // ---- layer 0 ----
    gather_bf16_kernel<<<GG, 256>>>(xb, agg);
    mlp_mma<128><<<GB, 256, SMF128>>>(agg, whi + 0*32768, bA[0], whi + 1*32768, bB[0], h1);
    stats_kernel<128><<<SG, 256>>>(h1);
    bn_finalize_kernel<<<1, 128>>>(gam[0], bet[0], 128);
    bn_apply_kernel<<<AG, 256>>>(h1);

    // ---- layer 1 ----
    gather_bf16_kernel<<<GG, 256>>>(hbnb, agg);
    mlp_mma<128><<<GB, 256, SMF128>>>(agg, whi + 2*32768, bA[1], whi + 3*32768, bB[1], h2);
    stats_kernel<128><<<SG, 256>>>(h2);
    bn_finalize_kernel<<<1, 128>>>(gam[1], bet[1], 128);
    bn_apply_kernel<<<AG, 256>>>(h2);

    // ---- layer 2 ----
    gather_bf16_kernel<<<GG, 256>>>(hbnb, agg);
    mlp_mma<64><<<GB, 256, SMF64>>>(agg, whi + 4*32768, bA[2], whi + 5*32768, bB[2], h1);
    stats_kernel<64><<<SG, 256>>>(h1);
    bn_finalize_kernel<<<1, 64>>>(gam[2], bet[2], 64);

    // ---- global mean pool (BN+ReLU fused) ----
    pool_sum_kernel<<<(NN * 16 + 255)/256, 256>>>(h1, batch);
    pool_cnt_kernel<<<296, 256>>>(batch);
    pool_fin_kernel<<<(NGR * DO_ + 255)/256, 256>>>((float*)d_out);
}

// round 16
// speedup vs baseline: 2.2748x; 1.2022x over previous
#include <cuda_runtime.h>
#include <cuda_bf16.h>
#include <cstdint>

#define NN   100000
#define NE   1600000
#define NGR  128
#define D_   128
#define DO_  64
#define BN_EPS 1e-5f
#define SCAN_ELEMS 2048
#define NBLK ((NN + SCAN_ELEMS - 1) / SCAN_ELEMS)   // 49

typedef unsigned long long ull;

// ---------------- scratch ----------------
__device__ __align__(16) __nv_bfloat16 g_aggb[(size_t)NN * D_];        // bf16 gather output
__device__ __align__(16) __nv_bfloat16 g_xb [(size_t)NN * D_];         // bf16 x
__device__ __align__(16) __nv_bfloat16 g_h1 [(size_t)NN * D_];         // bf16 pre-BN h
__device__ __align__(16) __nv_bfloat16 g_h2 [(size_t)NN * D_];
__device__ __align__(16) __nv_bfloat16 g_hbnb[(size_t)NN * D_];        // bf16 post-BN h
__device__ __align__(16) float g_bnstats[2 * D_];
__device__ __align__(16) float g_scale[D_];
__device__ __align__(16) float g_shift[D_];
__device__ __align__(16) float g_pool[NGR * DO_];
__device__ __align__(16) int   g_cnt[NGR];
__device__ int g_statctr;
// CSR scratch
__device__ __align__(16) int g_deg[NN];
__device__ __align__(16) int g_off[NN + 1];
__device__ __align__(16) int g_cur[NN];
__device__ __align__(16) int g_csr[NE];
__device__ int g_bsum[64];
__device__ int g_bscan[64];
// bf16-rounded, pre-swizzled W images
__device__ __align__(16) unsigned char g_whi[6 * 32768];

// ---------------- asm helpers ----------------
__device__ __forceinline__ uint32_t smem_u32(const void* p) {
    uint32_t a;
    asm("{ .reg .u64 t; cvta.to.shared.u64 t, %1; cvt.u32.u64 %0, t; }" : "=r"(a) : "l"(p));
    return a;
}
__device__ __forceinline__ ull add2(ull a, ull b) {
    ull r;
    asm("add.rn.f32x2 %0, %1, %2;" : "=l"(r) : "l"(a), "l"(b));
    return r;
}
__device__ __forceinline__ ull bexp(uint32_t v) {
    return ((ull)(v & 0xffff0000u) << 32) | (ull)(v << 16);
}
__device__ __forceinline__ float4 bexp4(uint2 r) {
    float4 o;
    o.x = __uint_as_float(r.x << 16);
    o.y = __uint_as_float(r.x & 0xffff0000u);
    o.z = __uint_as_float(r.y << 16);
    o.w = __uint_as_float(r.y & 0xffff0000u);
    return o;
}
__device__ __forceinline__ uint32_t pack_bf2(ull p) {
    __nv_bfloat162 b;
    b.x = __float2bfloat16(__uint_as_float((uint32_t)p));
    b.y = __float2bfloat16(__uint_as_float((uint32_t)(p >> 32)));
    return *(uint32_t*)&b;
}
__device__ __forceinline__ void ldsm_x4(uint32_t& r0, uint32_t& r1, uint32_t& r2, uint32_t& r3,
                                        uint32_t addr) {
    asm volatile("ldmatrix.sync.aligned.m8n8.x4.shared.b16 {%0,%1,%2,%3}, [%4];"
                 : "=r"(r0), "=r"(r1), "=r"(r2), "=r"(r3) : "r"(addr));
}
__device__ __forceinline__ void ldsm_x4t(uint32_t& r0, uint32_t& r1, uint32_t& r2, uint32_t& r3,
                                         uint32_t addr) {
    asm volatile("ldmatrix.sync.aligned.m8n8.x4.trans.shared.b16 {%0,%1,%2,%3}, [%4];"
                 : "=r"(r0), "=r"(r1), "=r"(r2), "=r"(r3) : "r"(addr));
}
__device__ __forceinline__ void mma16816(float* c, uint32_t a0, uint32_t a1, uint32_t a2,
                                         uint32_t a3, uint32_t b0, uint32_t b1) {
    asm volatile("mma.sync.aligned.m16n8k16.row.col.f32.bf16.bf16.f32 "
                 "{%0,%1,%2,%3}, {%4,%5,%6,%7}, {%8,%9}, {%0,%1,%2,%3};"
                 : "+f"(c[0]), "+f"(c[1]), "+f"(c[2]), "+f"(c[3])
                 : "r"(a0), "r"(a1), "r"(a2), "r"(a3), "r"(b0), "r"(b1));
}

// ---------------- CSR build ----------------
__global__ void hist_kernel(const int* __restrict__ dst) {
    int i = blockIdx.x * blockDim.x + threadIdx.x;
    if (i < NE) atomicAdd(&g_deg[__ldg(dst + i)], 1);
}
__global__ void scan_pass1() {
    __shared__ int ssum[8];
    int b = blockIdx.x, tid = threadIdx.x;
    int base = b * SCAN_ELEMS + tid * 8;
    int s = 0;
    #pragma unroll
    for (int j = 0; j < 8; j++) { int idx = base + j; s += (idx < NN) ? g_deg[idx] : 0; }
    #pragma unroll
    for (int o = 16; o; o >>= 1) s += __shfl_down_sync(0xffffffffu, s, o);
    if ((tid & 31) == 0) ssum[tid >> 5] = s;
    __syncthreads();
    if (tid == 0) {
        int t = 0;
        #pragma unroll
        for (int i = 0; i < 8; i++) t += ssum[i];
        g_bsum[b] = t;
    }
}
__global__ void scan_pass2() {
    int tid = threadIdx.x;
    int v = (tid < NBLK) ? g_bsum[tid] : 0;
    int incl = v, lane = tid & 31;
    #pragma unroll
    for (int o = 1; o < 32; o <<= 1) {
        int y = __shfl_up_sync(0xffffffffu, incl, o);
        if (lane >= o) incl += y;
    }
    __shared__ int w0;
    if (tid == 31) w0 = incl;
    __syncthreads();
    if (tid >= 32) incl += w0;
    if (tid < 64) g_bscan[tid] = incl - v;
    if (tid == 0) g_off[NN] = NE;
}
__global__ void scan_pass3() {
    int b = blockIdx.x, tid = threadIdx.x;
    int base = b * SCAN_ELEMS + tid * 8;
    int vals[8], t = 0;
    #pragma unroll
    for (int j = 0; j < 8; j++) { vals[j] = (base + j < NN) ? g_deg[base + j] : 0; t += vals[j]; }
    int lane = tid & 31, wid = tid >> 5, incl = t;
    #pragma unroll
    for (int o = 1; o < 32; o <<= 1) {
        int y = __shfl_up_sync(0xffffffffu, incl, o);
        if (lane >= o) incl += y;
    }
    __shared__ int wsum[8], woff[8];
    if (lane == 31) wsum[wid] = incl;
    __syncthreads();
    if (tid == 0) { int a = 0; for (int i = 0; i < 8; i++) { woff[i] = a; a += wsum[i]; } }
    __syncthreads();
    int run = g_bscan[b] + woff[wid] + (incl - t);
    #pragma unroll
    for (int j = 0; j < 8; j++) {
        int idx = base + j;
        if (idx < NN) {
            g_off[idx] = run; g_cur[idx] = run; run += vals[j];
            g_deg[idx] = 0;
        }
    }
}
__global__ void fill_kernel(const int* __restrict__ src, const int* __restrict__ dst) {
    int i = blockIdx.x * blockDim.x + threadIdx.x;
    if (i < NE) {
        int d = __ldg(dst + i);
        int p = atomicAdd(&g_cur[d], 1);
        g_csr[p] = __ldg(src + i);
    }
}

// ---------------- prep: x->bf16, W->bf16 swizzled, pool count histogram ----------------
__global__ void prep_kernel(const float* __restrict__ x,
                            const float* w0, const float* w1, const float* w2,
                            const float* w3, const float* w4, const float* w5,
                            const int* __restrict__ batch)
{
    int i = blockIdx.x * blockDim.x + threadIdx.x;
    if (i < NN * 32) {
        float4 v = __ldg((const float4*)x + i);
        __nv_bfloat162 p0, p1;
        p0.x = __float2bfloat16(v.x); p0.y = __float2bfloat16(v.y);
        p1.x = __float2bfloat16(v.z); p1.y = __float2bfloat16(v.w);
        uint2 o;
        o.x = *(uint32_t*)&p0; o.y = *(uint32_t*)&p1;
        ((uint2*)g_xb)[i] = o;
    }
    if (i < 5 * 16384 + 8192) {
        int seg = i >> 14;
        int t = i & 16383;
        int nout = (seg == 5) ? 64 : 128;
        const float* W = (seg == 0) ? w0 : (seg == 1) ? w1 : (seg == 2) ? w2
                       : (seg == 3) ? w3 : (seg == 4) ? w4 : w5;
        int k = t / nout, n = t % nout;
        float w = __ldg(W + k * nout + n);
        int pos = k * nout + ((((n >> 3) ^ (k & 7)) << 3) | (n & 7));
        ((__nv_bfloat16*)(g_whi + seg * 32768))[pos] = __float2bfloat16(w);
    }
    if (i < NN) {
        // batch is sorted -> warp-uniform addresses -> ptxas REDUX aggregation
        atomicAdd(&g_cnt[__ldg(batch + i)], 1);
    }
}

// ---------------- pure-sum gather, bf16 in / bf16 out ----------------
__global__ void gather_bf16_kernel(const __nv_bfloat16* __restrict__ hsrc,
                                   __nv_bfloat16* __restrict__ out)
{
    int n = blockIdx.x * 8 + (threadIdx.x >> 5);
    if (n >= NN) return;
    int lane = threadIdx.x & 31;
    const uint2* __restrict__ hb = (const uint2*)hsrc;

    uint2 s = __ldg(&hb[(size_t)n * 32 + lane]);
    ull a0 = bexp(s.x), b0 = bexp(s.y);
    ull a1 = 0, b1 = 0, a2 = 0, b2 = 0, a3 = 0, b3 = 0;

    int j = g_off[n], e1 = g_off[n + 1];
    for (; j + 4 <= e1; j += 4) {
        int i0 = __ldg(&g_csr[j]);
        int i1 = __ldg(&g_csr[j + 1]);
        int i2 = __ldg(&g_csr[j + 2]);
        int i3 = __ldg(&g_csr[j + 3]);
        uint2 w0 = __ldg(&hb[(size_t)i0 * 32 + lane]);
        uint2 w1 = __ldg(&hb[(size_t)i1 * 32 + lane]);
        uint2 w2 = __ldg(&hb[(size_t)i2 * 32 + lane]);
        uint2 w3 = __ldg(&hb[(size_t)i3 * 32 + lane]);
        a0 = add2(a0, bexp(w0.x)); b0 = add2(b0, bexp(w0.y));
        a1 = add2(a1, bexp(w1.x)); b1 = add2(b1, bexp(w1.y));
        a2 = add2(a2, bexp(w2.x)); b2 = add2(b2, bexp(w2.y));
        a3 = add2(a3, bexp(w3.x)); b3 = add2(b3, bexp(w3.y));
    }
    for (; j < e1; j++) {
        int sidx = __ldg(&g_csr[j]);
        uint2 w = __ldg(&hb[(size_t)sidx * 32 + lane]);
        a0 = add2(a0, bexp(w.x)); b0 = add2(b0, bexp(w.y));
    }
    a0 = add2(add2(a0, a1), add2(a2, a3));
    b0 = add2(add2(b0, b1), add2(b2, b3));
    uint2 o;
    o.x = pack_bf2(a0);
    o.y = pack_bf2(b0);
    ((uint2*)out)[(size_t)n * 32 + lane] = o;
}

// ---------------- BN+ReLU apply: bf16 h -> bf16 hbn ----------------
__global__ void bn_apply_kernel(const __nv_bfloat16* __restrict__ pre)
{
    int i = blockIdx.x * blockDim.x + threadIdx.x;
    if (i >= NN * 32) return;
    int c = (i & 31) << 2;
    float4 v  = bexp4(__ldg((const uint2*)pre + i));
    float4 sc = *(const float4*)(g_scale + c);
    float4 sh = *(const float4*)(g_shift + c);
    v.x = fmaxf(fmaf(v.x, sc.x, sh.x), 0.f);
    v.y = fmaxf(fmaf(v.y, sc.y, sh.y), 0.f);
    v.z = fmaxf(fmaf(v.z, sc.z, sh.z), 0.f);
    v.w = fmaxf(fmaf(v.w, sc.w, sh.w), 0.f);
    __nv_bfloat162 p0, p1;
    p0.x = __float2bfloat16(v.x); p0.y = __float2bfloat16(v.y);
    p1.x = __float2bfloat16(v.z); p1.y = __float2bfloat16(v.w);
    uint2 o;
    o.x = *(uint32_t*)&p0; o.y = *(uint32_t*)&p1;
    ((uint2*)g_hbnb)[i] = o;
}

// ---------------- 1-term mma_loop: A @ B, both bf16 ----------------
template<int NT>
__device__ __forceinline__ void mma_loop1(uint32_t sb, uint32_t aOff, uint32_t bOff,
                                          int wid, int lane, float acc[][4])
{
    const int la = lane & 15;
    const int lb = lane >> 4;
    const int l7 = lane & 7;
    const int BR = NT * 16;
    const uint32_t aRow = (uint32_t)((wid * 16 + la) * 256);
    const uint32_t bRow = (uint32_t)(la * BR);
    #pragma unroll 2
    for (int k0 = 0; k0 < 128; k0 += 16) {
        uint32_t kc = (uint32_t)((k0 >> 3) + lb);
        uint32_t aoff = aRow + ((kc ^ (uint32_t)l7) << 4);
        uint32_t a0, a1, a2, a3;
        ldsm_x4(a0, a1, a2, a3, sb + aOff + aoff);
        uint32_t bbase = (uint32_t)(k0 * BR) + bRow;
        #pragma unroll
        for (int nt = 0; nt < NT; nt += 2) {
            uint32_t boff = bbase + ((((uint32_t)(nt + lb)) ^ (uint32_t)l7) << 4);
            uint32_t bh0, bh1, bh2, bh3;
            ldsm_x4t(bh0, bh1, bh2, bh3, sb + bOff + boff);
            mma16816(acc[nt],     a0, a1, a2, a3, bh0, bh1);
            mma16816(acc[nt + 1], a0, a1, a2, a3, bh2, bh3);
        }
    }
}

// ---------------- fused 2-GEMM MLP (all-bf16 operands, fp32 accum) ----------------
template<int NOUT>
__global__ __launch_bounds__(256, 2)
void mlp_mma(const __nv_bfloat16* __restrict__ A,
             const unsigned char* __restrict__ w1h, const float* __restrict__ b1,
             const unsigned char* __restrict__ w2h, const float* __restrict__ b2,
             __nv_bfloat16* __restrict__ out)
{
    constexpr int NT2  = NOUT / 8;
    constexpr int AOF  = 0;
    constexpr int B1OF = 32768;
    constexpr int B2OF = 65536;

    extern __shared__ __align__(16) char smem[];
    const uint32_t sb = smem_u32(smem);
    const int tid  = threadIdx.x;
    const int wid  = tid >> 5;
    const int lane = tid & 31;
    const int row0 = blockIdx.x * 128;

    // B tiles
    {
        const float4* s1 = (const float4*)w1h;
        float4* d1 = (float4*)(smem + B1OF);
        #pragma unroll
        for (int i = tid; i < 2048; i += 256) d1[i] = s1[i];
        const float4* s3 = (const float4*)w2h;
        float4* d3 = (float4*)(smem + B2OF);
        #pragma unroll
        for (int i = tid; i < NOUT * 16; i += 256) d3[i] = s3[i];
    }
    // A tile: bf16 rows, swizzled 16B chunks
    for (int i = tid; i < 2048; i += 256) {
        int r = i >> 4, c = i & 15;
        int gr = row0 + r;
        uint4 v = make_uint4(0, 0, 0, 0);
        if (gr < NN) v = __ldg((const uint4*)(A + (size_t)gr * 128) + c);
        uint32_t off = (uint32_t)(r * 256 + ((c ^ (r & 7)) << 4));
        *(uint4*)(smem + AOF + off) = v;
    }
    __syncthreads();

    // stage 1
    float acc[16][4];
    #pragma unroll
    for (int t = 0; t < 16; t++)
        #pragma unroll
        for (int e = 0; e < 4; e++) acc[t][e] = 0.f;
    mma_loop1<16>(sb, AOF, B1OF, wid, lane, acc);
    __syncthreads();

    // epilogue 1: bias+ReLU, bf16, write back into A buffer
    {
        int rr1 = wid * 16 + (lane >> 2);
        int rr2 = rr1 + 8;
        uint32_t cb1 = (uint32_t)(rr1 * 256);
        uint32_t cb2 = (uint32_t)(rr2 * 256);
        int sw1 = (rr1 & 7), sw2 = (rr2 & 7);
        int cpos = (lane & 3) * 4;
        #pragma unroll
        for (int nt = 0; nt < 16; nt++) {
            int col = nt * 8 + (lane & 3) * 2;
            float2 bb = __ldg((const float2*)(b1 + col));
            float v0 = fmaxf(acc[nt][0] + bb.x, 0.f);
            float v1 = fmaxf(acc[nt][1] + bb.y, 0.f);
            float v2 = fmaxf(acc[nt][2] + bb.x, 0.f);
            float v3 = fmaxf(acc[nt][3] + bb.y, 0.f);
            __nv_bfloat162 h2;
            h2.x = __float2bfloat16(v0);
            h2.y = __float2bfloat16(v1);
            uint32_t o1 = cb1 + ((uint32_t)(nt ^ sw1) << 4) + cpos;
            *(uint32_t*)(smem + AOF + o1) = *(uint32_t*)&h2;
            h2.x = __float2bfloat16(v2);
            h2.y = __float2bfloat16(v3);
            uint32_t o2 = cb2 + ((uint32_t)(nt ^ sw2) << 4) + cpos;
            *(uint32_t*)(smem + AOF + o2) = *(uint32_t*)&h2;
        }
    }
    __syncthreads();

    // stage 2
    float acc2[NT2][4];
    #pragma unroll
    for (int t = 0; t < NT2; t++)
        #pragma unroll
        for (int e = 0; e < 4; e++) acc2[t][e] = 0.f;
    mma_loop1<NT2>(sb, AOF, B2OF, wid, lane, acc2);

    int r1 = row0 + wid * 16 + (lane >> 2);
    int r2 = r1 + 8;
    #pragma unroll
    for (int nt = 0; nt < NT2; nt++) {
        int col = nt * 8 + (lane & 3) * 2;
        float2 bb = __ldg((const float2*)(b2 + col));
        float v0 = acc2[nt][0] + bb.x;
        float v1 = acc2[nt][1] + bb.y;
        float v2 = acc2[nt][2] + bb.x;
        float v3 = acc2[nt][3] + bb.y;
        if (r1 < NN) {
            __nv_bfloat162 p;
            p.x = __float2bfloat16(v0); p.y = __float2bfloat16(v1);
            *(uint32_t*)(out + (size_t)r1 * NOUT + col) = *(uint32_t*)&p;
        }
        if (r2 < NN) {
            __nv_bfloat162 p;
            p.x = __float2bfloat16(v2); p.y = __float2bfloat16(v3);
            *(uint32_t*)(out + (size_t)r2 * NOUT + col) = *(uint32_t*)&p;
        }
    }
}

// ---------------- BN column stats + fused finalize (last-block pattern) ----------------
template<int NOUT>
__global__ void stats_kernel(const __nv_bfloat16* __restrict__ h,
                             const float* __restrict__ gamma,
                             const float* __restrict__ beta)
{
    constexpr int QC = NOUT / 4;
    constexpr int STEP = 256 / QC;
    __shared__ float ss[NOUT], sq[NOUT];
    __shared__ int isLast;
    int tid = threadIdx.x;
    if (tid < NOUT) { ss[tid] = 0.f; sq[tid] = 0.f; }
    __syncthreads();
    int qc = tid % QC, rg = tid / QC;
    int rend = min(blockIdx.x * 512 + 512, NN);
    float4 s4 = make_float4(0,0,0,0), q4 = make_float4(0,0,0,0);
    for (int r = blockIdx.x * 512 + rg; r < rend; r += STEP) {
        float4 v = bexp4(__ldg((const uint2*)h + (size_t)r * QC + qc));
        s4.x += v.x; s4.y += v.y; s4.z += v.z; s4.w += v.w;
        q4.x += v.x*v.x; q4.y += v.y*v.y; q4.z += v.z*v.z; q4.w += v.w*v.w;
    }
    int c = qc * 4;
    atomicAdd(&ss[c+0], s4.x); atomicAdd(&ss[c+1], s4.y);
    atomicAdd(&ss[c+2], s4.z); atomicAdd(&ss[c+3], s4.w);
    atomicAdd(&sq[c+0], q4.x); atomicAdd(&sq[c+1], q4.y);
    atomicAdd(&sq[c+2], q4.z); atomicAdd(&sq[c+3], q4.w);
    __syncthreads();
    if (tid < NOUT) {
        atomicAdd(&g_bnstats[tid], ss[tid]);
        atomicAdd(&g_bnstats[NOUT + tid], sq[tid]);
    }
    __threadfence();
    if (tid == 0) isLast = (atomicAdd(&g_statctr, 1) == (int)gridDim.x - 1);
    __syncthreads();
    if (isLast) {
        __threadfence();
        if (tid < NOUT) {
            const float invN = 1.0f / (float)NN;
            float sv = g_bnstats[tid];
            float qv = g_bnstats[NOUT + tid];
            float mu  = sv * invN;
            float var = qv * invN - mu * mu;
            float s   = gamma[tid] * rsqrtf(var + BN_EPS);
            g_scale[tid] = s;
            g_shift[tid] = beta[tid] - mu * s;
            g_bnstats[tid] = 0.f;
            g_bnstats[NOUT + tid] = 0.f;
        }
        if (tid == 0) g_statctr = 0;
    }
}

// ---------------- pooling (BN+ReLU fused, bf16 input) ----------------
__global__ void pool_sum_kernel(const __nv_bfloat16* __restrict__ pre,
                                const int* __restrict__ batch)
{
    int t = blockIdx.x * blockDim.x + threadIdx.x;
    if (t >= NN * 16) return;
    int n = t >> 4, q = t & 15;
    int c = q << 2;
    int b = __ldg(batch + n);
    float4 v  = bexp4(__ldg((const uint2*)pre + (size_t)n * 16 + q));
    float4 sc = *(const float4*)(g_scale + c);
    float4 sh = *(const float4*)(g_shift + c);
    v.x = fmaxf(fmaf(v.x, sc.x, sh.x), 0.f);
    v.y = fmaxf(fmaf(v.y, sc.y, sh.y), 0.f);
    v.z = fmaxf(fmaf(v.z, sc.z, sh.z), 0.f);
    v.w = fmaxf(fmaf(v.w, sc.w, sh.w), 0.f);
    float* p = g_pool + b * DO_ + c;
    asm volatile("red.global.add.v4.f32 [%0], {%1, %2, %3, %4};"
                 :: "l"(p), "f"(v.x), "f"(v.y), "f"(v.z), "f"(v.w) : "memory");
}

// ---------------- pool finalize (self-resets pool & cnt for next replay) ----------------
__global__ void pool_fin_kernel(float* __restrict__ out)
{
    int i = blockIdx.x * blockDim.x + threadIdx.x;
    if (i < NGR * DO_) {
        int g = i >> 6;
        int cv = g_cnt[g];
        float c = (float)(cv > 0 ? cv : 1);
        out[i] = g_pool[i] / c;
        g_pool[i] = 0.f;
    }
    __syncthreads();
    if (i < NGR * DO_ && (i & 63) == 0) g_cnt[i >> 6] = 0;
}

// ---------------- launcher ----------------
extern "C" void kernel_launch(void* const* d_in, const int* in_sizes, int n_in,
                              void* d_out, int out_size)
{
    const float* x     = (const float*)d_in[0];
    const int*   ei    = (const int*)d_in[1];
    const int*   batch = (const int*)d_in[2];
    const float *wA[3], *bA[3], *wB[3], *bB[3], *gam[3], *bet[3];
    for (int l = 0; l < 3; l++) {
        wA[l]  = (const float*)d_in[3 + 6*l + 0];
        bA[l]  = (const float*)d_in[3 + 6*l + 1];
        wB[l]  = (const float*)d_in[3 + 6*l + 2];
        bB[l]  = (const float*)d_in[3 + 6*l + 3];
        gam[l] = (const float*)d_in[3 + 6*l + 4];
        bet[l] = (const float*)d_in[3 + 6*l + 5];
    }
    const int* src = ei;
    const int* dst = ei + NE;

    __nv_bfloat16 *aggb, *xb, *h1, *h2, *hbnb;
    unsigned char *whi;
    cudaGetSymbolAddress((void**)&aggb, g_aggb);
    cudaGetSymbolAddress((void**)&xb,   g_xb);
    cudaGetSymbolAddress((void**)&h1,   g_h1);
    cudaGetSymbolAddress((void**)&h2,   g_h2);
    cudaGetSymbolAddress((void**)&hbnb, g_hbnb);
    cudaGetSymbolAddress((void**)&whi,  g_whi);

    constexpr int SMF128 = 32768 + 32768 + 32768;  // 98304
    constexpr int SMF64  = 32768 + 32768 + 16384;  // 81920
    cudaFuncSetAttribute(mlp_mma<128>, cudaFuncAttributeMaxDynamicSharedMemorySize, SMF128);
    cudaFuncSetAttribute(mlp_mma<64>,  cudaFuncAttributeMaxDynamicSharedMemorySize, SMF64);

    const int GB = (NN + 127) / 128;   // 782
    const int EG = (NE + 255) / 256;
    const int GG = (NN + 7) / 8;
    const int SG = (NN + 511) / 512;
    const int AG = (NN * 32 + 255) / 256;

    // ---- CSR build ----
    hist_kernel<<<EG, 256>>>(dst);
    scan_pass1<<<NBLK, 256>>>();
    scan_pass2<<<1, 64>>>();
    scan_pass3<<<NBLK, 256>>>();
    fill_kernel<<<EG, 256>>>(src, dst);

    // ---- prep: x->bf16, W->bf16 swizzled, pool count ----
    prep_kernel<<<AG, 256>>>(x, wA[0], wB[0], wA[1], wB[1], wA[2], wB[2], batch);

    // ---- layer 0 ----
    gather_bf16_kernel<<<GG, 256>>>(xb, aggb);
    mlp_mma<128><<<GB, 256, SMF128>>>(aggb, whi + 0*32768, bA[0], whi + 1*32768, bB[0], h1);
    stats_kernel<128><<<SG, 256>>>(h1, gam[0], bet[0]);
    bn_apply_kernel<<<AG, 256>>>(h1);

    // ---- layer 1 ----
    gather_bf16_kernel<<<GG, 256>>>(hbnb, aggb);
    mlp_mma<128><<<GB, 256, SMF128>>>(aggb, whi + 2*32768, bA[1], whi + 3*32768, bB[1], h2);
    stats_kernel<128><<<SG, 256>>>(h2, gam[1], bet[1]);
    bn_apply_kernel<<<AG, 256>>>(h2);

    // ---- layer 2 ----
    gather_bf16_kernel<<<GG, 256>>>(hbnb, aggb);
    mlp_mma<64><<<GB, 256, SMF64>>>(aggb, whi + 4*32768, bA[2], whi + 5*32768, bB[2], h1);
    stats_kernel<64><<<SG, 256>>>(h1, gam[2], bet[2]);

    // ---- global mean pool (BN+ReLU fused) ----
    pool_sum_kernel<<<(NN * 16 + 255)/256, 256>>>(h1, batch);
    pool_fin_kernel<<<(NGR * DO_ + 255)/256, 256>>>((float*)d_out);
}